// round 12
// baseline (speedup 1.0000x reference)
#include <cuda_runtime.h>
#include <math.h>

#define NB     8
#define TT     4096
#define HID    4096
#define NSAMP  512
#define NSLOT  16
#define DD     256
#define BOTD   512
#define EPSF   1e-5f

// ---------------- scratch (no allocations allowed) ----------------
__device__ float g_pre    [NB*NSAMP*DD];
__device__ float g_x      [NB*NSAMP*DD];
__device__ float g_k      [NB*NSAMP*DD];
__device__ float g_v      [NB*NSAMP*DD];
__device__ int   g_idx    [NSAMP];
__device__ float g_tpart  [16*NB*HID];
__device__ float g_target [NB*HID];
__device__ float g_slots  [NB*NSLOT*DD];
__device__ float g_s      [NB*NSLOT*DD];
__device__ float g_q      [NB*NSLOT*DD];
__device__ float g_updpart[NB*8*NSLOT*DD];   // (b,chunk,k,d)
__device__ float g_r2     [NB*NSLOT*BOTD];
__device__ float g_rbar   [NB*BOTD];
__device__ float g_recon  [NB*HID];

// ---------------- helpers ----------------
__device__ __forceinline__ float warpSum(float v){
#pragma unroll
    for (int o = 16; o > 0; o >>= 1) v += __shfl_xor_sync(0xffffffffu, v, o);
    return v;
}
__device__ __forceinline__ float geluf(float x){
    return 0.5f * x * (1.0f + erff(x * 0.7071067811865475f));
}

// ---------------- idx = concat(linspace(0,T-256,256).astype(i32), arange(T-256,T)) ----------------
__global__ void k_init_idx(){
    int i = threadIdx.x;
    if (i < 256) {
        const float delta = 3840.0f / 255.0f;     // fp32, matches jnp.linspace step
        g_idx[i] = (int)((float)i * delta);       // truncation == astype(int32)
    } else {
        g_idx[i] = 3840 + (i - 256);
    }
}

// ---------------- target mean: partial sums over 256-step t chunks ----------------
__global__ void __launch_bounds__(256) k_mean_part(const float* __restrict__ hs){
    int hb = blockIdx.x * 1024 + threadIdx.x * 4;
    int b  = blockIdx.y, c = blockIdx.z;
    const float* p = hs + ((size_t)b*TT + (size_t)c*256)*HID + hb;
    float4 acc0 = make_float4(0,0,0,0), acc1 = make_float4(0,0,0,0);
#pragma unroll 4
    for (int t = 0; t < 256; t += 2) {
        float4 v0 = *(const float4*)(p + (size_t)t*HID);
        float4 v1 = *(const float4*)(p + (size_t)(t+1)*HID);
        acc0.x += v0.x; acc0.y += v0.y; acc0.z += v0.z; acc0.w += v0.w;
        acc1.x += v1.x; acc1.y += v1.y; acc1.z += v1.z; acc1.w += v1.w;
    }
    float4 acc = make_float4(acc0.x+acc1.x, acc0.y+acc1.y, acc0.z+acc1.z, acc0.w+acc1.w);
    *(float4*)&g_tpart[((size_t)c*NB + b)*HID + hb] = acc;
}

__global__ void k_mean_reduce(){
    int gi = blockIdx.x * 256 + threadIdx.x;   // gi = b*HID + h, 32768 total
    float s = 0.f;
#pragma unroll
    for (int c = 0; c < 16; c++) s += g_tpart[(size_t)c*NB*HID + gi];
    g_target[gi] = s * (1.0f / (float)TT);
}

// ---------------- SGEMM 64x64x16, 256 thr, 4x4 microtile. N fixed = 256. ----------------
// mode 0: A = gathered hidden rows, B=in_w, C=g_pre (+bias)
// mode 1: A = g_x, B=k_w, C=g_k      mode 2: A = g_x, B=v_w, C=g_v
__global__ void __launch_bounds__(256) k_sgemm(const float* __restrict__ hs,
                                               const float* __restrict__ Bw,
                                               const float* __restrict__ bias,
                                               int Kdim, int mode){
    __shared__ __align__(16) float As[16][64];
    __shared__ __align__(16) float Bs[16][64];
    int tid  = threadIdx.x;
    int brow = blockIdx.y * 64, bcol = blockIdx.x * 64;
    int arow = tid >> 2, ak = (tid & 3) * 4;
    int r    = brow + arow;
    const float* Arow;
    if (mode == 0) {
        int bb = r >> 9; int t = g_idx[r & 511];
        Arow = hs + ((size_t)(bb*TT + t))*HID;
    } else {
        Arow = g_x + (size_t)r * DD;
    }
    float* C = (mode == 0) ? g_pre : (mode == 1 ? g_k : g_v);
    int brr = tid >> 4, bc = (tid & 15) * 4;
    int ty  = tid >> 4, tx = tid & 15;
    float acc[4][4] = {};
    for (int k0 = 0; k0 < Kdim; k0 += 16) {
        float4 a4 = *(const float4*)(Arow + k0 + ak);
        float4 b4 = *(const float4*)(Bw + (size_t)(k0 + brr)*256 + bcol + bc);
        As[ak+0][arow] = a4.x; As[ak+1][arow] = a4.y;
        As[ak+2][arow] = a4.z; As[ak+3][arow] = a4.w;
        *(float4*)&Bs[brr][bc] = b4;
        __syncthreads();
#pragma unroll
        for (int kk = 0; kk < 16; kk++) {
            float4 av = *(const float4*)&As[kk][ty*4];
            float4 bv = *(const float4*)&Bs[kk][tx*4];
            acc[0][0]+=av.x*bv.x; acc[0][1]+=av.x*bv.y; acc[0][2]+=av.x*bv.z; acc[0][3]+=av.x*bv.w;
            acc[1][0]+=av.y*bv.x; acc[1][1]+=av.y*bv.y; acc[1][2]+=av.y*bv.z; acc[1][3]+=av.y*bv.w;
            acc[2][0]+=av.z*bv.x; acc[2][1]+=av.z*bv.y; acc[2][2]+=av.z*bv.z; acc[2][3]+=av.z*bv.w;
            acc[3][0]+=av.w*bv.x; acc[3][1]+=av.w*bv.y; acc[3][2]+=av.w*bv.z; acc[3][3]+=av.w*bv.w;
        }
        __syncthreads();
    }
#pragma unroll
    for (int i = 0; i < 4; i++) {
#pragma unroll
        for (int j = 0; j < 4; j++) {
            int col = bcol + tx*4 + j;
            float bv = bias ? bias[col] : 0.f;
            C[(size_t)(brow + ty*4 + i)*256 + col] = acc[i][j] + bv;
        }
    }
}

// ---------------- LayerNorm of g_pre rows -> g_x ----------------
__global__ void __launch_bounds__(256) k_ln(const float* __restrict__ gg, const float* __restrict__ bb){
    __shared__ float buf[256];
    int r = blockIdx.x, tid = threadIdx.x;
    float v = g_pre[(size_t)r*256 + tid];
    buf[tid] = v; __syncthreads();
    for (int s = 128; s > 0; s >>= 1) { if (tid < s) buf[tid] += buf[tid + s]; __syncthreads(); }
    float mu = buf[0] * (1.f/256.f); __syncthreads();
    float d = v - mu;
    buf[tid] = d * d; __syncthreads();
    for (int s = 128; s > 0; s >>= 1) { if (tid < s) buf[tid] += buf[tid + s]; __syncthreads(); }
    float var = buf[0] * (1.f/256.f);
    g_x[(size_t)r*256 + tid] = d * rsqrtf(var + EPSF) * gg[tid] + bb[tid];
}

// ---------------- slots init ----------------
__global__ void k_copy_in(const float* __restrict__ src){
    int i = blockIdx.x * 256 + threadIdx.x;
    g_slots[i] = src[i];
}

// ---------------- per-iteration: s=LN(slots), q=s@q_w (4 rows per block) ----------------
__global__ void __launch_bounds__(256) k_slotlnq(const float* __restrict__ qw,
                                                 const float* __restrict__ lg,
                                                 const float* __restrict__ lb){
    __shared__ float sm[4][256];
    int tid = threadIdx.x, warp = tid >> 5, lane = tid & 31;
    int b = blockIdx.x >> 2, r0 = (blockIdx.x & 3) * 4;
    if (warp < 4) {
        int row = b*16 + r0 + warp;
        float v[8]; float s1 = 0.f;
#pragma unroll
        for (int j = 0; j < 8; j++) { v[j] = g_slots[(size_t)row*256 + lane + 32*j]; s1 += v[j]; }
        s1 = warpSum(s1); float mu = s1 * (1.f/256.f);
        float s2 = 0.f;
#pragma unroll
        for (int j = 0; j < 8; j++) { float dd = v[j] - mu; s2 += dd*dd; }
        s2 = warpSum(s2); float rs = rsqrtf(s2 * (1.f/256.f) + EPSF);
#pragma unroll
        for (int j = 0; j < 8; j++) {
            int d = lane + 32*j;
            float sv = (v[j] - mu) * rs * lg[d] + lb[d];
            sm[warp][d] = sv;
            g_s[(size_t)row*256 + d] = sv;
        }
    }
    __syncthreads();
    float a0=0,a1=0,a2=0,a3=0;
    for (int d = 0; d < 256; d++) {
        float w = qw[(size_t)d*256 + tid];
        a0 += sm[0][d]*w; a1 += sm[1][d]*w; a2 += sm[2][d]*w; a3 += sm[3][d]*w;
    }
    int base = (b*16 + r0) * 256;
    g_q[base       + tid] = a0;
    g_q[base + 256 + tid] = a1;
    g_q[base + 512 + tid] = a2;
    g_q[base + 768 + tid] = a3;
}

// ---------------- logits + softmax(over slots) + partial upd ----------------
__global__ void __launch_bounds__(256) k_attn(){
    __shared__ __align__(16) float qs[16][260];
    __shared__ __align__(16) float ksh[8][260];
    __shared__ float attn_s[64][16];
    int tid = threadIdx.x;
    int chunk = blockIdx.x, b = blockIdx.y;
#pragma unroll
    for (int i = 0; i < 16; i++) qs[i][tid] = g_q[(size_t)(b*NSLOT + i)*DD + tid];
    __syncthreads();
    int warp = tid >> 5, lane = tid & 31;
    for (int step = 0; step < 8; step++) {
        int nl = step*8 + warp;
        const float* kr = g_k + ((size_t)(b*NSAMP + chunk*64 + nl))*DD;
#pragma unroll
        for (int j = 0; j < 8; j++) ksh[warp][lane + 32*j] = kr[lane + 32*j];
        __syncwarp();
        float logit = -1e30f;
        if (lane < 16) {
            float a = 0.f;
#pragma unroll 8
            for (int d = 0; d < 256; d += 4) {
                float4 qv = *(const float4*)&qs[lane][d];
                float4 kv = *(const float4*)&ksh[warp][d];
                a += qv.x*kv.x + qv.y*kv.y + qv.z*kv.z + qv.w*kv.w;
            }
            logit = a * 0.0625f;           // D^-0.5
        }
        float m = logit;
#pragma unroll
        for (int o = 8; o > 0; o >>= 1) m = fmaxf(m, __shfl_xor_sync(0xffffffffu, m, o));
        float e = expf(logit - m);
        float ss = e;
#pragma unroll
        for (int o = 8; o > 0; o >>= 1) ss += __shfl_xor_sync(0xffffffffu, ss, o);
        if (lane < 16) attn_s[nl][lane] = e / ss;
        __syncwarp();
    }
    __syncthreads();
    float acc[16];
#pragma unroll
    for (int kk = 0; kk < 16; kk++) acc[kk] = 0.f;
    for (int nl = 0; nl < 64; nl++) {
        float vv = g_v[((size_t)(b*NSAMP + chunk*64 + nl))*DD + tid];
#pragma unroll
        for (int kk = 0; kk < 16; kk++) acc[kk] += attn_s[nl][kk] * vv;
    }
#pragma unroll
    for (int kk = 0; kk < 16; kk++)
        g_updpart[((size_t)(b*8 + chunk))*(NSLOT*DD) + kk*DD + tid] = acc[kk];
}

// ---------------- reduce partials + LN + MLP + slot update (4 rows / block) ----------------
__global__ void __launch_bounds__(512) k_updmlp(const float* __restrict__ lmg, const float* __restrict__ lmb,
                                                const float* __restrict__ w1,  const float* __restrict__ b1,
                                                const float* __restrict__ w2,  const float* __restrict__ b2){
    __shared__ float usm[4][256];
    __shared__ float hsm[4][256];
    __shared__ float gsm[4][512];
    int tid = threadIdx.x;
    int b = blockIdx.x >> 2, r0 = (blockIdx.x & 3) * 4;
    for (int idx = tid; idx < 1024; idx += 512) {
        int row = idx >> 8, d = idx & 255;
        float u = 0.f;
#pragma unroll
        for (int c = 0; c < 8; c++)
            u += g_updpart[((size_t)(b*8 + c))*(NSLOT*DD) + (size_t)(r0 + row)*DD + d];
        usm[row][d] = u;
    }
    __syncthreads();
    int warp = tid >> 5, lane = tid & 31;
    if (warp < 4) {
        float v[8]; float s1 = 0.f;
#pragma unroll
        for (int j = 0; j < 8; j++) { v[j] = usm[warp][lane + 32*j]; s1 += v[j]; }
        s1 = warpSum(s1); float mu = s1 * (1.f/256.f);
        float s2 = 0.f;
#pragma unroll
        for (int j = 0; j < 8; j++) { float dd = v[j] - mu; s2 += dd*dd; }
        s2 = warpSum(s2); float rs = rsqrtf(s2 * (1.f/256.f) + EPSF);
#pragma unroll
        for (int j = 0; j < 8; j++) {
            int d = lane + 32*j;
            hsm[warp][d] = (v[j] - mu) * rs * lmg[d] + lmb[d];
        }
    }
    __syncthreads();
    float a0 = b1[tid], a1 = a0, a2 = a0, a3 = a0;
    for (int d = 0; d < 256; d++) {
        float w = w1[(size_t)d*512 + tid];
        a0 += hsm[0][d]*w; a1 += hsm[1][d]*w; a2 += hsm[2][d]*w; a3 += hsm[3][d]*w;
    }
    gsm[0][tid] = geluf(a0); gsm[1][tid] = geluf(a1);
    gsm[2][tid] = geluf(a2); gsm[3][tid] = geluf(a3);
    __syncthreads();
    if (tid < 256) {
        float m0=0,m1=0,m2=0,m3=0;
        for (int j = 0; j < 512; j++) {
            float w = w2[(size_t)j*256 + tid];
            m0 += gsm[0][j]*w; m1 += gsm[1][j]*w; m2 += gsm[2][j]*w; m3 += gsm[3][j]*w;
        }
        float bb = b2[tid];
        int base = (b*16 + r0) * 256;
        g_slots[base       + tid] = g_s[base       + tid] + m0 + bb;
        g_slots[base + 256 + tid] = g_s[base + 256 + tid] + m1 + bb;
        g_slots[base + 512 + tid] = g_s[base + 512 + tid] + m2 + bb;
        g_slots[base + 768 + tid] = g_s[base + 768 + tid] + m3 + bb;
    }
}

// ---------------- decoder stage 1+2 (4 rows / block) ----------------
__global__ void __launch_bounds__(512) k_dec1(const float* __restrict__ w1, const float* __restrict__ b1,
                                              const float* __restrict__ w2, const float* __restrict__ b2){
    __shared__ float ssm[4][256];
    __shared__ float g1[4][512];
    int tid = threadIdx.x;
    int r0 = blockIdx.x * 4;
    for (int idx = tid; idx < 1024; idx += 512)
        ssm[idx >> 8][idx & 255] = g_slots[(size_t)(r0 + (idx >> 8))*256 + (idx & 255)];
    __syncthreads();
    float a0 = b1[tid], a1 = a0, a2 = a0, a3 = a0;
    for (int d = 0; d < 256; d++) {
        float w = w1[(size_t)d*512 + tid];
        a0 += ssm[0][d]*w; a1 += ssm[1][d]*w; a2 += ssm[2][d]*w; a3 += ssm[3][d]*w;
    }
    g1[0][tid] = geluf(a0); g1[1][tid] = geluf(a1);
    g1[2][tid] = geluf(a2); g1[3][tid] = geluf(a3);
    __syncthreads();
    float c0 = b2[tid], c1 = c0, c2 = c0, c3 = c0;
    for (int j = 0; j < 512; j++) {
        float w = w2[(size_t)j*512 + tid];
        c0 += g1[0][j]*w; c1 += g1[1][j]*w; c2 += g1[2][j]*w; c3 += g1[3][j]*w;
    }
    g_r2[(size_t)(r0+0)*512 + tid] = geluf(c0);
    g_r2[(size_t)(r0+1)*512 + tid] = geluf(c1);
    g_r2[(size_t)(r0+2)*512 + tid] = geluf(c2);
    g_r2[(size_t)(r0+3)*512 + tid] = geluf(c3);
}

__global__ void k_rbar(){
    int gi = blockIdx.x * 256 + threadIdx.x;   // 4096 = 8 * 512
    int b = gi >> 9, j = gi & 511;
    float s = 0.f;
#pragma unroll
    for (int kk = 0; kk < 16; kk++) s += g_r2[(size_t)(b*16 + kk)*512 + j];
    g_rbar[gi] = s * (1.f/16.f);
}

__global__ void __launch_bounds__(128) k_recon(const float* __restrict__ w3, const float* __restrict__ b3){
    __shared__ float rb[8][512];
    int tid = threadIdx.x;
    for (int idx = tid; idx < 4096; idx += 128) rb[idx >> 9][idx & 511] = g_rbar[idx];
    __syncthreads();
    int h = blockIdx.x * 128 + tid;
    float bv = b3[h];
    float acc[8];
#pragma unroll
    for (int b = 0; b < 8; b++) acc[b] = bv;
    for (int j = 0; j < 512; j++) {
        float w = w3[(size_t)j*HID + h];
#pragma unroll
        for (int b = 0; b < 8; b++) acc[b] += rb[b][j] * w;
    }
#pragma unroll
    for (int b = 0; b < 8; b++) g_recon[(size_t)b*HID + h] = acc[b];
}

__global__ void __launch_bounds__(1024) k_loss(float* __restrict__ out, int out_size){
    __shared__ float buf[1024];
    int tid = threadIdx.x;
    float s = 0.f;
    for (int i = tid; i < NB*HID; i += 1024) {
        float dd = g_recon[i] - g_target[i];
        s += dd * dd;
    }
    buf[tid] = s; __syncthreads();
    for (int st = 512; st > 0; st >>= 1) { if (tid < st) buf[tid] += buf[tid + st]; __syncthreads(); }
    if (tid == 0) out[out_size - 1] = buf[0] * (1.f / (float)(NB*HID));
}

__global__ void k_copy_out(float* __restrict__ out, int out_size){
    int i = blockIdx.x * 256 + threadIdx.x;
    if (i < NB*NSLOT*DD && i < out_size) out[i] = g_slots[i];
}

// ---------------- launcher ----------------
extern "C" void kernel_launch(void* const* d_in, const int* in_sizes, int n_in,
                              void* d_out, int out_size){
    const float* hs        = (const float*)d_in[0];
    const float* old_slots = (const float*)d_in[1];
    const float* in_w      = (const float*)d_in[2];
    const float* in_b      = (const float*)d_in[3];
    const float* ln_in_g   = (const float*)d_in[4];
    const float* ln_in_b   = (const float*)d_in[5];
    const float* ln_s_g    = (const float*)d_in[6];
    const float* ln_s_b    = (const float*)d_in[7];
    const float* ln_m_g    = (const float*)d_in[8];
    const float* ln_m_b    = (const float*)d_in[9];
    const float* q_w       = (const float*)d_in[10];
    const float* k_w       = (const float*)d_in[11];
    const float* v_w       = (const float*)d_in[12];
    const float* mlp_w1    = (const float*)d_in[13];
    const float* mlp_b1    = (const float*)d_in[14];
    const float* mlp_w2    = (const float*)d_in[15];
    const float* mlp_b2    = (const float*)d_in[16];
    const float* dec_w1    = (const float*)d_in[17];
    const float* dec_b1    = (const float*)d_in[18];
    const float* dec_w2    = (const float*)d_in[19];
    const float* dec_b2    = (const float*)d_in[20];
    const float* dec_w3    = (const float*)d_in[21];
    const float* dec_b3    = (const float*)d_in[22];
    float* out = (float*)d_out;

    k_init_idx<<<1, 512>>>();
    k_mean_part<<<dim3(4, 8, 16), 256>>>(hs);
    k_mean_reduce<<<128, 256>>>();

    k_sgemm<<<dim3(4, 64), 256>>>(hs, in_w, in_b, HID, 0);   // pre = gather(hidden)@in_w + in_b
    k_ln<<<NB*NSAMP, 256>>>(ln_in_g, ln_in_b);               // x = LN(pre)
    k_sgemm<<<dim3(4, 64), 256>>>(hs, k_w, nullptr, DD, 1);  // k = x@k_w
    k_sgemm<<<dim3(4, 64), 256>>>(hs, v_w, nullptr, DD, 2);  // v = x@v_w

    k_copy_in<<<128, 256>>>(old_slots);
    for (int it = 0; it < 3; it++) {
        k_slotlnq<<<32, 256>>>(q_w, ln_s_g, ln_s_b);
        k_attn<<<dim3(8, 8), 256>>>();
        k_updmlp<<<32, 512>>>(ln_m_g, ln_m_b, mlp_w1, mlp_b1, mlp_w2, mlp_b2);
    }

    k_dec1<<<32, 512>>>(dec_w1, dec_b1, dec_w2, dec_b2);
    k_rbar<<<16, 256>>>();
    k_recon<<<32, 128>>>(dec_w3, dec_b3);
    k_loss<<<1, 1024>>>(out, out_size);
    k_copy_out<<<128, 256>>>(out, out_size);
}

// round 13
// speedup vs baseline: 1.3764x; 1.3764x over previous
#include <cuda_runtime.h>
#include <math.h>

#define NB     8
#define TT     4096
#define HID    4096
#define NSAMP  512
#define NSLOT  16
#define DD     256
#define BOTD   512
#define EPSF   1e-5f
#define KSPLIT 8
#define KCHUNK 512   // HID / KSPLIT

// ---------------- scratch (no allocations allowed) ----------------
__device__ float g_gpart  [KSPLIT*NB*NSAMP*DD];   // 32 MB K-split partials
__device__ float g_x      [NB*NSAMP*DD];
__device__ float g_k      [NB*NSAMP*DD];
__device__ float g_v      [NB*NSAMP*DD];
__device__ int   g_idx    [NSAMP];
__device__ float g_tpart  [16*NB*HID];
__device__ float g_target [NB*HID];
__device__ float g_slots  [NB*NSLOT*DD];
__device__ float g_s      [NB*NSLOT*DD];
__device__ float g_q      [NB*NSLOT*DD];
__device__ float g_updpart[NB*8*NSLOT*DD];   // (b,chunk,k,d)
__device__ float g_r2     [NB*NSLOT*BOTD];
__device__ float g_rbar   [NB*BOTD];
__device__ float g_recon  [NB*HID];

// ---------------- helpers ----------------
__device__ __forceinline__ float warpSum(float v){
#pragma unroll
    for (int o = 16; o > 0; o >>= 1) v += __shfl_xor_sync(0xffffffffu, v, o);
    return v;
}
__device__ __forceinline__ float geluf(float x){
    return 0.5f * x * (1.0f + erff(x * 0.7071067811865475f));
}

// ---------------- idx = concat(linspace(0,T-256,256).astype(i32), arange(T-256,T)) ----------------
__global__ void k_init_idx(){
    int i = threadIdx.x;
    if (i < 256) {
        const float delta = 3840.0f / 255.0f;     // fp32, matches jnp.linspace step
        g_idx[i] = (int)((float)i * delta);       // truncation == astype(int32)
    } else {
        g_idx[i] = 3840 + (i - 256);
    }
}

// ---------------- target mean: partial sums over 256-step t chunks ----------------
__global__ void __launch_bounds__(256) k_mean_part(const float* __restrict__ hs){
    int hb = blockIdx.x * 1024 + threadIdx.x * 4;
    int b  = blockIdx.y, c = blockIdx.z;
    const float* p = hs + ((size_t)b*TT + (size_t)c*256)*HID + hb;
    float4 acc0 = make_float4(0,0,0,0), acc1 = make_float4(0,0,0,0);
#pragma unroll 4
    for (int t = 0; t < 256; t += 2) {
        float4 v0 = *(const float4*)(p + (size_t)t*HID);
        float4 v1 = *(const float4*)(p + (size_t)(t+1)*HID);
        acc0.x += v0.x; acc0.y += v0.y; acc0.z += v0.z; acc0.w += v0.w;
        acc1.x += v1.x; acc1.y += v1.y; acc1.z += v1.z; acc1.w += v1.w;
    }
    float4 acc = make_float4(acc0.x+acc1.x, acc0.y+acc1.y, acc0.z+acc1.z, acc0.w+acc1.w);
    *(float4*)&g_tpart[((size_t)c*NB + b)*HID + hb] = acc;
}

__global__ void k_mean_reduce(){
    int gi = blockIdx.x * 256 + threadIdx.x;   // gi = b*HID + h, 32768 total
    float s = 0.f;
#pragma unroll
    for (int c = 0; c < 16; c++) s += g_tpart[(size_t)c*NB*HID + gi];
    g_target[gi] = s * (1.0f / (float)TT);
}

// ---------------- K-split gather GEMM: 64x64 tile, K-chunk 512, double-buffered ----------------
// grid = (4, 64, KSPLIT).  partial[ks][row][col] = sum over K chunk ks of gathered_A @ in_w
__global__ void __launch_bounds__(256) k_gemm0(const float* __restrict__ hs,
                                               const float* __restrict__ Bw){
    __shared__ __align__(16) float As[2][16][64];
    __shared__ __align__(16) float Bs[2][16][64];
    int tid  = threadIdx.x;
    int bcol = blockIdx.x * 64, brow = blockIdx.y * 64, ks = blockIdx.z;
    int arow = tid >> 2, ak = (tid & 3) * 4;
    int r    = brow + arow;
    int bb   = r >> 9; int t = g_idx[r & 511];
    const float* Arow = hs + ((size_t)(bb*TT + t))*HID + ks*KCHUNK;
    const float* Bp   = Bw + (size_t)(ks*KCHUNK)*256 + bcol;
    int brr = tid >> 4, bc = (tid & 15) * 4;
    int ty  = tid >> 4, tx = tid & 15;
    float acc[4][4] = {};

    float4 a4 = *(const float4*)(Arow + ak);
    float4 b4 = *(const float4*)(Bp + (size_t)brr*256 + bc);
    As[0][ak+0][arow] = a4.x; As[0][ak+1][arow] = a4.y;
    As[0][ak+2][arow] = a4.z; As[0][ak+3][arow] = a4.w;
    *(float4*)&Bs[0][brr][bc] = b4;
    __syncthreads();

    int buf = 0;
#pragma unroll 1
    for (int kt = 0; kt < KCHUNK/16; kt++) {
        if (kt < KCHUNK/16 - 1) {
            a4 = *(const float4*)(Arow + (kt+1)*16 + ak);
            b4 = *(const float4*)(Bp + (size_t)((kt+1)*16 + brr)*256 + bc);
        }
#pragma unroll
        for (int kk = 0; kk < 16; kk++) {
            float4 av = *(const float4*)&As[buf][kk][ty*4];
            float4 bv = *(const float4*)&Bs[buf][kk][tx*4];
            acc[0][0]+=av.x*bv.x; acc[0][1]+=av.x*bv.y; acc[0][2]+=av.x*bv.z; acc[0][3]+=av.x*bv.w;
            acc[1][0]+=av.y*bv.x; acc[1][1]+=av.y*bv.y; acc[1][2]+=av.y*bv.z; acc[1][3]+=av.y*bv.w;
            acc[2][0]+=av.z*bv.x; acc[2][1]+=av.z*bv.y; acc[2][2]+=av.z*bv.z; acc[2][3]+=av.z*bv.w;
            acc[3][0]+=av.w*bv.x; acc[3][1]+=av.w*bv.y; acc[3][2]+=av.w*bv.z; acc[3][3]+=av.w*bv.w;
        }
        if (kt < KCHUNK/16 - 1) {
            int nb = buf ^ 1;
            As[nb][ak+0][arow] = a4.x; As[nb][ak+1][arow] = a4.y;
            As[nb][ak+2][arow] = a4.z; As[nb][ak+3][arow] = a4.w;
            *(float4*)&Bs[nb][brr][bc] = b4;
            buf = nb;
            __syncthreads();
        }
    }
    float* C = g_gpart + (size_t)ks*(NB*NSAMP*DD);
#pragma unroll
    for (int i = 0; i < 4; i++)
#pragma unroll
        for (int j = 0; j < 4; j++)
            C[(size_t)(brow + ty*4 + i)*256 + bcol + tx*4 + j] = acc[i][j];
}

// ---------------- reduce K-split partials + bias + LayerNorm -> g_x (fused) ----------------
__global__ void __launch_bounds__(256) k_redln(const float* __restrict__ bias,
                                               const float* __restrict__ gg,
                                               const float* __restrict__ bb){
    __shared__ float buf[256];
    int r = blockIdx.x, tid = threadIdx.x;
    float v = bias[tid];
#pragma unroll
    for (int s = 0; s < KSPLIT; s++)
        v += g_gpart[(size_t)s*(NB*NSAMP*DD) + (size_t)r*256 + tid];
    buf[tid] = v; __syncthreads();
    for (int s = 128; s > 0; s >>= 1) { if (tid < s) buf[tid] += buf[tid + s]; __syncthreads(); }
    float mu = buf[0] * (1.f/256.f); __syncthreads();
    float d = v - mu;
    buf[tid] = d * d; __syncthreads();
    for (int s = 128; s > 0; s >>= 1) { if (tid < s) buf[tid] += buf[tid + s]; __syncthreads(); }
    float var = buf[0] * (1.f/256.f);
    g_x[(size_t)r*256 + tid] = d * rsqrtf(var + EPSF) * gg[tid] + bb[tid];
}

// ---------------- k/v projections in one launch: grid (4, 64, 2), K=256, double-buffered ----------------
__global__ void __launch_bounds__(256) k_gemmkv(const float* __restrict__ kw,
                                                const float* __restrict__ vw){
    __shared__ __align__(16) float As[2][16][64];
    __shared__ __align__(16) float Bs[2][16][64];
    int tid  = threadIdx.x;
    int bcol = blockIdx.x * 64, brow = blockIdx.y * 64;
    const float* Bw = blockIdx.z ? vw : kw;
    float* C        = blockIdx.z ? g_v : g_k;
    int arow = tid >> 2, ak = (tid & 3) * 4;
    const float* Arow = g_x + (size_t)(brow + arow) * DD;
    int brr = tid >> 4, bc = (tid & 15) * 4;
    int ty  = tid >> 4, tx = tid & 15;
    float acc[4][4] = {};

    float4 a4 = *(const float4*)(Arow + ak);
    float4 b4 = *(const float4*)(Bw + (size_t)brr*256 + bcol + bc);
    As[0][ak+0][arow] = a4.x; As[0][ak+1][arow] = a4.y;
    As[0][ak+2][arow] = a4.z; As[0][ak+3][arow] = a4.w;
    *(float4*)&Bs[0][brr][bc] = b4;
    __syncthreads();

    int buf = 0;
#pragma unroll 1
    for (int kt = 0; kt < 16; kt++) {
        if (kt < 15) {
            a4 = *(const float4*)(Arow + (kt+1)*16 + ak);
            b4 = *(const float4*)(Bw + (size_t)((kt+1)*16 + brr)*256 + bcol + bc);
        }
#pragma unroll
        for (int kk = 0; kk < 16; kk++) {
            float4 av = *(const float4*)&As[buf][kk][ty*4];
            float4 bv = *(const float4*)&Bs[buf][kk][tx*4];
            acc[0][0]+=av.x*bv.x; acc[0][1]+=av.x*bv.y; acc[0][2]+=av.x*bv.z; acc[0][3]+=av.x*bv.w;
            acc[1][0]+=av.y*bv.x; acc[1][1]+=av.y*bv.y; acc[1][2]+=av.y*bv.z; acc[1][3]+=av.y*bv.w;
            acc[2][0]+=av.z*bv.x; acc[2][1]+=av.z*bv.y; acc[2][2]+=av.z*bv.z; acc[2][3]+=av.z*bv.w;
            acc[3][0]+=av.w*bv.x; acc[3][1]+=av.w*bv.y; acc[3][2]+=av.w*bv.z; acc[3][3]+=av.w*bv.w;
        }
        if (kt < 15) {
            int nb = buf ^ 1;
            As[nb][ak+0][arow] = a4.x; As[nb][ak+1][arow] = a4.y;
            As[nb][ak+2][arow] = a4.z; As[nb][ak+3][arow] = a4.w;
            *(float4*)&Bs[nb][brr][bc] = b4;
            buf = nb;
            __syncthreads();
        }
    }
#pragma unroll
    for (int i = 0; i < 4; i++)
#pragma unroll
        for (int j = 0; j < 4; j++)
            C[(size_t)(brow + ty*4 + i)*256 + bcol + tx*4 + j] = acc[i][j];
}

// ---------------- slots init ----------------
__global__ void k_copy_in(const float* __restrict__ src){
    int i = blockIdx.x * 256 + threadIdx.x;
    g_slots[i] = src[i];
}

// ---------------- per-iteration: s=LN(slots), q=s@q_w (4 rows per block) ----------------
__global__ void __launch_bounds__(256) k_slotlnq(const float* __restrict__ qw,
                                                 const float* __restrict__ lg,
                                                 const float* __restrict__ lb){
    __shared__ float sm[4][256];
    int tid = threadIdx.x, warp = tid >> 5, lane = tid & 31;
    int b = blockIdx.x >> 2, r0 = (blockIdx.x & 3) * 4;
    if (warp < 4) {
        int row = b*16 + r0 + warp;
        float v[8]; float s1 = 0.f;
#pragma unroll
        for (int j = 0; j < 8; j++) { v[j] = g_slots[(size_t)row*256 + lane + 32*j]; s1 += v[j]; }
        s1 = warpSum(s1); float mu = s1 * (1.f/256.f);
        float s2 = 0.f;
#pragma unroll
        for (int j = 0; j < 8; j++) { float dd = v[j] - mu; s2 += dd*dd; }
        s2 = warpSum(s2); float rs = rsqrtf(s2 * (1.f/256.f) + EPSF);
#pragma unroll
        for (int j = 0; j < 8; j++) {
            int d = lane + 32*j;
            float sv = (v[j] - mu) * rs * lg[d] + lb[d];
            sm[warp][d] = sv;
            g_s[(size_t)row*256 + d] = sv;
        }
    }
    __syncthreads();
    float a0=0,a1=0,a2=0,a3=0;
    for (int d = 0; d < 256; d++) {
        float w = qw[(size_t)d*256 + tid];
        a0 += sm[0][d]*w; a1 += sm[1][d]*w; a2 += sm[2][d]*w; a3 += sm[3][d]*w;
    }
    int base = (b*16 + r0) * 256;
    g_q[base       + tid] = a0;
    g_q[base + 256 + tid] = a1;
    g_q[base + 512 + tid] = a2;
    g_q[base + 768 + tid] = a3;
}

// ---------------- logits + softmax(over slots) + partial upd ----------------
__global__ void __launch_bounds__(256) k_attn(){
    __shared__ __align__(16) float qs[16][260];
    __shared__ __align__(16) float ksh[8][260];
    __shared__ float attn_s[64][16];
    int tid = threadIdx.x;
    int chunk = blockIdx.x, b = blockIdx.y;
#pragma unroll
    for (int i = 0; i < 16; i++) qs[i][tid] = g_q[(size_t)(b*NSLOT + i)*DD + tid];
    __syncthreads();
    int warp = tid >> 5, lane = tid & 31;
    for (int step = 0; step < 8; step++) {
        int nl = step*8 + warp;
        const float* kr = g_k + ((size_t)(b*NSAMP + chunk*64 + nl))*DD;
#pragma unroll
        for (int j = 0; j < 8; j++) ksh[warp][lane + 32*j] = kr[lane + 32*j];
        __syncwarp();
        float logit = -1e30f;
        if (lane < 16) {
            float a = 0.f;
#pragma unroll 8
            for (int d = 0; d < 256; d += 4) {
                float4 qv = *(const float4*)&qs[lane][d];
                float4 kv = *(const float4*)&ksh[warp][d];
                a += qv.x*kv.x + qv.y*kv.y + qv.z*kv.z + qv.w*kv.w;
            }
            logit = a * 0.0625f;           // D^-0.5
        }
        float m = logit;
#pragma unroll
        for (int o = 8; o > 0; o >>= 1) m = fmaxf(m, __shfl_xor_sync(0xffffffffu, m, o));
        float e = expf(logit - m);
        float ss = e;
#pragma unroll
        for (int o = 8; o > 0; o >>= 1) ss += __shfl_xor_sync(0xffffffffu, ss, o);
        if (lane < 16) attn_s[nl][lane] = e / ss;
        __syncwarp();
    }
    __syncthreads();
    float acc[16];
#pragma unroll
    for (int kk = 0; kk < 16; kk++) acc[kk] = 0.f;
    for (int nl = 0; nl < 64; nl++) {
        float vv = g_v[((size_t)(b*NSAMP + chunk*64 + nl))*DD + tid];
#pragma unroll
        for (int kk = 0; kk < 16; kk++) acc[kk] += attn_s[nl][kk] * vv;
    }
#pragma unroll
    for (int kk = 0; kk < 16; kk++)
        g_updpart[((size_t)(b*8 + chunk))*(NSLOT*DD) + kk*DD + tid] = acc[kk];
}

// ---------------- reduce partials + LN + MLP + slot update (4 rows / block) ----------------
__global__ void __launch_bounds__(512) k_updmlp(const float* __restrict__ lmg, const float* __restrict__ lmb,
                                                const float* __restrict__ w1,  const float* __restrict__ b1,
                                                const float* __restrict__ w2,  const float* __restrict__ b2){
    __shared__ float usm[4][256];
    __shared__ float hsm[4][256];
    __shared__ float gsm[4][512];
    int tid = threadIdx.x;
    int b = blockIdx.x >> 2, r0 = (blockIdx.x & 3) * 4;
    for (int idx = tid; idx < 1024; idx += 512) {
        int row = idx >> 8, d = idx & 255;
        float u = 0.f;
#pragma unroll
        for (int c = 0; c < 8; c++)
            u += g_updpart[((size_t)(b*8 + c))*(NSLOT*DD) + (size_t)(r0 + row)*DD + d];
        usm[row][d] = u;
    }
    __syncthreads();
    int warp = tid >> 5, lane = tid & 31;
    if (warp < 4) {
        float v[8]; float s1 = 0.f;
#pragma unroll
        for (int j = 0; j < 8; j++) { v[j] = usm[warp][lane + 32*j]; s1 += v[j]; }
        s1 = warpSum(s1); float mu = s1 * (1.f/256.f);
        float s2 = 0.f;
#pragma unroll
        for (int j = 0; j < 8; j++) { float dd = v[j] - mu; s2 += dd*dd; }
        s2 = warpSum(s2); float rs = rsqrtf(s2 * (1.f/256.f) + EPSF);
#pragma unroll
        for (int j = 0; j < 8; j++) {
            int d = lane + 32*j;
            hsm[warp][d] = (v[j] - mu) * rs * lmg[d] + lmb[d];
        }
    }
    __syncthreads();
    float a0 = b1[tid], a1 = a0, a2 = a0, a3 = a0;
    for (int d = 0; d < 256; d++) {
        float w = w1[(size_t)d*512 + tid];
        a0 += hsm[0][d]*w; a1 += hsm[1][d]*w; a2 += hsm[2][d]*w; a3 += hsm[3][d]*w;
    }
    gsm[0][tid] = geluf(a0); gsm[1][tid] = geluf(a1);
    gsm[2][tid] = geluf(a2); gsm[3][tid] = geluf(a3);
    __syncthreads();
    if (tid < 256) {
        float m0=0,m1=0,m2=0,m3=0;
        for (int j = 0; j < 512; j++) {
            float w = w2[(size_t)j*256 + tid];
            m0 += gsm[0][j]*w; m1 += gsm[1][j]*w; m2 += gsm[2][j]*w; m3 += gsm[3][j]*w;
        }
        float bb = b2[tid];
        int base = (b*16 + r0) * 256;
        g_slots[base       + tid] = g_s[base       + tid] + m0 + bb;
        g_slots[base + 256 + tid] = g_s[base + 256 + tid] + m1 + bb;
        g_slots[base + 512 + tid] = g_s[base + 512 + tid] + m2 + bb;
        g_slots[base + 768 + tid] = g_s[base + 768 + tid] + m3 + bb;
    }
}

// ---------------- decoder stage 1+2 (4 rows / block) ----------------
__global__ void __launch_bounds__(512) k_dec1(const float* __restrict__ w1, const float* __restrict__ b1,
                                              const float* __restrict__ w2, const float* __restrict__ b2){
    __shared__ float ssm[4][256];
    __shared__ float g1[4][512];
    int tid = threadIdx.x;
    int r0 = blockIdx.x * 4;
    for (int idx = tid; idx < 1024; idx += 512)
        ssm[idx >> 8][idx & 255] = g_slots[(size_t)(r0 + (idx >> 8))*256 + (idx & 255)];
    __syncthreads();
    float a0 = b1[tid], a1 = a0, a2 = a0, a3 = a0;
    for (int d = 0; d < 256; d++) {
        float w = w1[(size_t)d*512 + tid];
        a0 += ssm[0][d]*w; a1 += ssm[1][d]*w; a2 += ssm[2][d]*w; a3 += ssm[3][d]*w;
    }
    g1[0][tid] = geluf(a0); g1[1][tid] = geluf(a1);
    g1[2][tid] = geluf(a2); g1[3][tid] = geluf(a3);
    __syncthreads();
    float c0 = b2[tid], c1 = c0, c2 = c0, c3 = c0;
    for (int j = 0; j < 512; j++) {
        float w = w2[(size_t)j*512 + tid];
        c0 += g1[0][j]*w; c1 += g1[1][j]*w; c2 += g1[2][j]*w; c3 += g1[3][j]*w;
    }
    g_r2[(size_t)(r0+0)*512 + tid] = geluf(c0);
    g_r2[(size_t)(r0+1)*512 + tid] = geluf(c1);
    g_r2[(size_t)(r0+2)*512 + tid] = geluf(c2);
    g_r2[(size_t)(r0+3)*512 + tid] = geluf(c3);
}

__global__ void k_rbar(){
    int gi = blockIdx.x * 256 + threadIdx.x;   // 4096 = 8 * 512
    int b = gi >> 9, j = gi & 511;
    float s = 0.f;
#pragma unroll
    for (int kk = 0; kk < 16; kk++) s += g_r2[(size_t)(b*16 + kk)*512 + j];
    g_rbar[gi] = s * (1.f/16.f);
}

__global__ void __launch_bounds__(128) k_recon(const float* __restrict__ w3, const float* __restrict__ b3){
    __shared__ float rb[8][512];
    int tid = threadIdx.x;
    for (int idx = tid; idx < 4096; idx += 128) rb[idx >> 9][idx & 511] = g_rbar[idx];
    __syncthreads();
    int h = blockIdx.x * 128 + tid;
    float bv = b3[h];
    float acc[8];
#pragma unroll
    for (int b = 0; b < 8; b++) acc[b] = bv;
    for (int j = 0; j < 512; j++) {
        float w = w3[(size_t)j*HID + h];
#pragma unroll
        for (int b = 0; b < 8; b++) acc[b] += rb[b][j] * w;
    }
#pragma unroll
    for (int b = 0; b < 8; b++) g_recon[(size_t)b*HID + h] = acc[b];
}

__global__ void __launch_bounds__(1024) k_loss(float* __restrict__ out, int out_size){
    __shared__ float buf[1024];
    int tid = threadIdx.x;
    float s = 0.f;
    for (int i = tid; i < NB*HID; i += 1024) {
        float dd = g_recon[i] - g_target[i];
        s += dd * dd;
    }
    buf[tid] = s; __syncthreads();
    for (int st = 512; st > 0; st >>= 1) { if (tid < st) buf[tid] += buf[tid + st]; __syncthreads(); }
    if (tid == 0) out[out_size - 1] = buf[0] * (1.f / (float)(NB*HID));
}

__global__ void k_copy_out(float* __restrict__ out, int out_size){
    int i = blockIdx.x * 256 + threadIdx.x;
    if (i < NB*NSLOT*DD && i < out_size) out[i] = g_slots[i];
}

// ---------------- launcher ----------------
extern "C" void kernel_launch(void* const* d_in, const int* in_sizes, int n_in,
                              void* d_out, int out_size){
    const float* hs        = (const float*)d_in[0];
    const float* old_slots = (const float*)d_in[1];
    const float* in_w      = (const float*)d_in[2];
    const float* in_b      = (const float*)d_in[3];
    const float* ln_in_g   = (const float*)d_in[4];
    const float* ln_in_b   = (const float*)d_in[5];
    const float* ln_s_g    = (const float*)d_in[6];
    const float* ln_s_b    = (const float*)d_in[7];
    const float* ln_m_g    = (const float*)d_in[8];
    const float* ln_m_b    = (const float*)d_in[9];
    const float* q_w       = (const float*)d_in[10];
    const float* k_w       = (const float*)d_in[11];
    const float* v_w       = (const float*)d_in[12];
    const float* mlp_w1    = (const float*)d_in[13];
    const float* mlp_b1    = (const float*)d_in[14];
    const float* mlp_w2    = (const float*)d_in[15];
    const float* mlp_b2    = (const float*)d_in[16];
    const float* dec_w1    = (const float*)d_in[17];
    const float* dec_b1    = (const float*)d_in[18];
    const float* dec_w2    = (const float*)d_in[19];
    const float* dec_b2    = (const float*)d_in[20];
    const float* dec_w3    = (const float*)d_in[21];
    const float* dec_b3    = (const float*)d_in[22];
    float* out = (float*)d_out;

    k_init_idx<<<1, 512>>>();

    // K-split gather GEMM (the former 470us hot spot): 2048 blocks
    k_gemm0<<<dim3(4, 64, KSPLIT), 256>>>(hs, in_w);
    k_redln<<<NB*NSAMP, 256>>>(in_b, ln_in_g, ln_in_b);      // reduce + bias + LN -> g_x
    k_gemmkv<<<dim3(4, 64, 2), 256>>>(k_w, v_w);             // k and v in one launch

    // target mean (independent; placed after GEMMs so tail overlaps small kernels)
    k_mean_part<<<dim3(4, 8, 16), 256>>>(hs);
    k_mean_reduce<<<128, 256>>>();

    k_copy_in<<<128, 256>>>(old_slots);
    for (int it = 0; it < 3; it++) {
        k_slotlnq<<<32, 256>>>(q_w, ln_s_g, ln_s_b);
        k_attn<<<dim3(8, 8), 256>>>();
        k_updmlp<<<32, 512>>>(ln_m_g, ln_m_b, mlp_w1, mlp_b1, mlp_w2, mlp_b2);
    }

    k_dec1<<<32, 512>>>(dec_w1, dec_b1, dec_w2, dec_b2);
    k_rbar<<<16, 256>>>();
    k_recon<<<32, 128>>>(dec_w3, dec_b3);
    k_loss<<<1, 1024>>>(out, out_size);
    k_copy_out<<<128, 256>>>(out, out_size);
}

// round 14
// speedup vs baseline: 1.4929x; 1.0847x over previous
#include <cuda_runtime.h>
#include <math.h>

#define NB     8
#define TT     4096
#define HID    4096
#define NSAMP  512
#define NSLOT  16
#define DD     256
#define BOTD   512
#define EPSF   1e-5f
#define KSPLIT 8
#define KCHUNK 512   // HID / KSPLIT
#define NKT    (KCHUNK/16)

// ---------------- scratch (no allocations allowed) ----------------
__device__ float g_gpart  [KSPLIT*NB*NSAMP*DD];   // 32 MB K-split partials
__device__ float g_x      [NB*NSAMP*DD];
__device__ float g_k      [NB*NSAMP*DD];
__device__ float g_v      [NB*NSAMP*DD];
__device__ int   g_idx    [NSAMP];
__device__ float g_tpart  [16*NB*HID];
__device__ float g_target [NB*HID];
__device__ float g_slots  [NB*NSLOT*DD];
__device__ float g_s      [NB*NSLOT*DD];
__device__ float g_q      [NB*NSLOT*DD];
__device__ float g_updpart[NB*8*NSLOT*DD];   // (b,chunk,k,d)
__device__ float g_r2     [NB*NSLOT*BOTD];
__device__ float g_rbar   [NB*BOTD];
__device__ float g_recon  [NB*HID];

// ---------------- helpers ----------------
__device__ __forceinline__ float warpSum(float v){
#pragma unroll
    for (int o = 16; o > 0; o >>= 1) v += __shfl_xor_sync(0xffffffffu, v, o);
    return v;
}
__device__ __forceinline__ float geluf(float x){
    return 0.5f * x * (1.0f + erff(x * 0.7071067811865475f));
}
__device__ __forceinline__ unsigned smem_u32(const void* p){
    return (unsigned)__cvta_generic_to_shared(p);
}
__device__ __forceinline__ void cpa16(unsigned dst, const void* src){
    asm volatile("cp.async.cg.shared.global [%0], [%1], 16;\n" :: "r"(dst), "l"(src));
}
__device__ __forceinline__ void cpa_commit(){ asm volatile("cp.async.commit_group;\n"); }
template<int N> __device__ __forceinline__ void cpa_wait(){
    asm volatile("cp.async.wait_group %0;\n" :: "n"(N));
}

// ---------------- idx = concat(linspace(0,T-256,256).astype(i32), arange(T-256,T)) ----------------
__global__ void k_init_idx(){
    int i = threadIdx.x;
    if (i < 256) {
        const float delta = 3840.0f / 255.0f;     // fp32, matches jnp.linspace step
        g_idx[i] = (int)((float)i * delta);       // truncation == astype(int32)
    } else {
        g_idx[i] = 3840 + (i - 256);
    }
}

// ===========================================================================
// k_front: interleaved fused launch, 1024 blocks of 256 threads.
//   odd  blocks (512): mean partial sums  (DRAM-bound)
//   even blocks (512): K-split gather GEMM, 128x128 tile, 8x8 microtile,
//                      cp.async double-buffered (FMA-bound)
// ===========================================================================
__global__ void __launch_bounds__(256, 2) k_front(const float* __restrict__ hs,
                                                  const float* __restrict__ Bw){
    __shared__ __align__(16) float As[2][128][16];
    __shared__ __align__(16) float Bs[2][16][128];
    int bid = blockIdx.x;
    int tid = threadIdx.x;

    if (bid & 1) {
        // ---------------- mean partial (b, 256-step t chunk, 1024-wide h chunk) --------
        int mid = bid >> 1;                 // 0..511
        int hb = (mid & 3) * 1024 + tid * 4;
        int b  = (mid >> 2) & 7;
        int c  = mid >> 5;
        const float* p = hs + ((size_t)b*TT + (size_t)c*256)*HID + hb;
        float4 acc0 = make_float4(0,0,0,0), acc1 = make_float4(0,0,0,0);
#pragma unroll 4
        for (int t = 0; t < 256; t += 2) {
            float4 v0 = *(const float4*)(p + (size_t)t*HID);
            float4 v1 = *(const float4*)(p + (size_t)(t+1)*HID);
            acc0.x += v0.x; acc0.y += v0.y; acc0.z += v0.z; acc0.w += v0.w;
            acc1.x += v1.x; acc1.y += v1.y; acc1.z += v1.z; acc1.w += v1.w;
        }
        float4 acc = make_float4(acc0.x+acc1.x, acc0.y+acc1.y, acc0.z+acc1.z, acc0.w+acc1.w);
        *(float4*)&g_tpart[((size_t)c*NB + b)*HID + hb] = acc;
        return;
    }

    // ---------------- gather GEMM block ----------------
    int gid  = bid >> 1;                    // 0..511
    int bcol = (gid & 1) * 128;
    int brow = ((gid >> 1) & 31) * 128;
    int ks   = gid >> 6;

    // A gather source rows (row-major [m][k] in smem, loaded via cp.async 16B)
    int r0 = brow + (tid >> 2);
    int r1 = r0 + 64;
    int ca = (tid & 3) * 4;
    const float* gA0 = hs + ((size_t)((r0 >> 9)*TT + g_idx[r0 & 511]))*HID + ks*KCHUNK + ca;
    const float* gA1 = hs + ((size_t)((r1 >> 9)*TT + g_idx[r1 & 511]))*HID + ks*KCHUNK + ca;
    // B source
    int kB = tid >> 5;
    int nB = (tid & 31) * 4;
    const float* gB0 = Bw + ((size_t)(ks*KCHUNK + kB))*256 + bcol + nB;
    const float* gB1 = gB0 + (size_t)8*256;

    unsigned sA0[2], sA1[2], sB0[2], sB1[2];
#pragma unroll
    for (int u = 0; u < 2; u++) {
        sA0[u] = smem_u32(&As[u][tid >> 2][ca]);
        sA1[u] = smem_u32(&As[u][(tid >> 2) + 64][ca]);
        sB0[u] = smem_u32(&Bs[u][kB][nB]);
        sB1[u] = smem_u32(&Bs[u][kB + 8][nB]);
    }

    // prologue: tile 0 -> buffer 0
    cpa16(sA0[0], gA0);
    cpa16(sA1[0], gA1);
    cpa16(sB0[0], gB0);
    cpa16(sB1[0], gB1);
    cpa_commit();

    float acc[8][8] = {};
    int ty = tid >> 4, tx = tid & 15;
    int buf = 0;

#pragma unroll 1
    for (int kt = 0; kt < NKT; kt++) {
        if (kt < NKT - 1) {
            int ko = (kt + 1) * 16;
            cpa16(sA0[buf ^ 1], gA0 + ko);
            cpa16(sA1[buf ^ 1], gA1 + ko);
            cpa16(sB0[buf ^ 1], gB0 + (size_t)ko*256);
            cpa16(sB1[buf ^ 1], gB1 + (size_t)ko*256);
            cpa_commit();
            cpa_wait<1>();          // tile kt is complete
        } else {
            cpa_wait<0>();
        }
        __syncthreads();
#pragma unroll
        for (int kk = 0; kk < 16; kk++) {
            float av[8];
#pragma unroll
            for (int i = 0; i < 8; i++) av[i] = As[buf][ty*8 + i][kk];   // broadcast loads
            float4 b0 = *(const float4*)&Bs[buf][kk][tx*4];
            float4 b1 = *(const float4*)&Bs[buf][kk][64 + tx*4];
#pragma unroll
            for (int i = 0; i < 8; i++) {
                acc[i][0] += av[i]*b0.x; acc[i][1] += av[i]*b0.y;
                acc[i][2] += av[i]*b0.z; acc[i][3] += av[i]*b0.w;
                acc[i][4] += av[i]*b1.x; acc[i][5] += av[i]*b1.y;
                acc[i][6] += av[i]*b1.z; acc[i][7] += av[i]*b1.w;
            }
        }
        __syncthreads();
        buf ^= 1;
    }

    float* C = g_gpart + (size_t)ks*(NB*NSAMP*DD);
#pragma unroll
    for (int i = 0; i < 8; i++) {
        size_t row = (size_t)(brow + ty*8 + i) * 256;
        *(float4*)&C[row + bcol + tx*4]      = make_float4(acc[i][0], acc[i][1], acc[i][2], acc[i][3]);
        *(float4*)&C[row + bcol + 64 + tx*4] = make_float4(acc[i][4], acc[i][5], acc[i][6], acc[i][7]);
    }
}

__global__ void k_mean_reduce(){
    int gi = blockIdx.x * 256 + threadIdx.x;   // gi = b*HID + h, 32768 total
    float s = 0.f;
#pragma unroll
    for (int c = 0; c < 16; c++) s += g_tpart[(size_t)c*NB*HID + gi];
    g_target[gi] = s * (1.0f / (float)TT);
}

// ---------------- reduce K-split partials + bias + LayerNorm -> g_x (fused) ----------------
__global__ void __launch_bounds__(256) k_redln(const float* __restrict__ bias,
                                               const float* __restrict__ gg,
                                               const float* __restrict__ bb){
    __shared__ float buf[256];
    int r = blockIdx.x, tid = threadIdx.x;
    float v = bias[tid];
#pragma unroll
    for (int s = 0; s < KSPLIT; s++)
        v += g_gpart[(size_t)s*(NB*NSAMP*DD) + (size_t)r*256 + tid];
    buf[tid] = v; __syncthreads();
    for (int s = 128; s > 0; s >>= 1) { if (tid < s) buf[tid] += buf[tid + s]; __syncthreads(); }
    float mu = buf[0] * (1.f/256.f); __syncthreads();
    float d = v - mu;
    buf[tid] = d * d; __syncthreads();
    for (int s = 128; s > 0; s >>= 1) { if (tid < s) buf[tid] += buf[tid + s]; __syncthreads(); }
    float var = buf[0] * (1.f/256.f);
    g_x[(size_t)r*256 + tid] = d * rsqrtf(var + EPSF) * gg[tid] + bb[tid];
}

// ---------------- k/v projections in one launch: grid (4, 64, 2), K=256, double-buffered ----------------
__global__ void __launch_bounds__(256) k_gemmkv(const float* __restrict__ kw,
                                                const float* __restrict__ vw){
    __shared__ __align__(16) float As[2][16][64];
    __shared__ __align__(16) float Bs[2][16][64];
    int tid  = threadIdx.x;
    int bcol = blockIdx.x * 64, brow = blockIdx.y * 64;
    const float* Bw = blockIdx.z ? vw : kw;
    float* C        = blockIdx.z ? g_v : g_k;
    int arow = tid >> 2, ak = (tid & 3) * 4;
    const float* Arow = g_x + (size_t)(brow + arow) * DD;
    int brr = tid >> 4, bc = (tid & 15) * 4;
    int ty  = tid >> 4, tx = tid & 15;
    float acc[4][4] = {};

    float4 a4 = *(const float4*)(Arow + ak);
    float4 b4 = *(const float4*)(Bw + (size_t)brr*256 + bcol + bc);
    As[0][ak+0][arow] = a4.x; As[0][ak+1][arow] = a4.y;
    As[0][ak+2][arow] = a4.z; As[0][ak+3][arow] = a4.w;
    *(float4*)&Bs[0][brr][bc] = b4;
    __syncthreads();

    int buf = 0;
#pragma unroll 1
    for (int kt = 0; kt < 16; kt++) {
        if (kt < 15) {
            a4 = *(const float4*)(Arow + (kt+1)*16 + ak);
            b4 = *(const float4*)(Bw + (size_t)((kt+1)*16 + brr)*256 + bcol + bc);
        }
#pragma unroll
        for (int kk = 0; kk < 16; kk++) {
            float4 av = *(const float4*)&As[buf][kk][ty*4];
            float4 bv = *(const float4*)&Bs[buf][kk][tx*4];
            acc[0][0]+=av.x*bv.x; acc[0][1]+=av.x*bv.y; acc[0][2]+=av.x*bv.z; acc[0][3]+=av.x*bv.w;
            acc[1][0]+=av.y*bv.x; acc[1][1]+=av.y*bv.y; acc[1][2]+=av.y*bv.z; acc[1][3]+=av.y*bv.w;
            acc[2][0]+=av.z*bv.x; acc[2][1]+=av.z*bv.y; acc[2][2]+=av.z*bv.z; acc[2][3]+=av.z*bv.w;
            acc[3][0]+=av.w*bv.x; acc[3][1]+=av.w*bv.y; acc[3][2]+=av.w*bv.z; acc[3][3]+=av.w*bv.w;
        }
        if (kt < 15) {
            int nb = buf ^ 1;
            As[nb][ak+0][arow] = a4.x; As[nb][ak+1][arow] = a4.y;
            As[nb][ak+2][arow] = a4.z; As[nb][ak+3][arow] = a4.w;
            *(float4*)&Bs[nb][brr][bc] = b4;
            buf = nb;
            __syncthreads();
        }
    }
#pragma unroll
    for (int i = 0; i < 4; i++)
#pragma unroll
        for (int j = 0; j < 4; j++)
            C[(size_t)(brow + ty*4 + i)*256 + bcol + tx*4 + j] = acc[i][j];
}

// ---------------- slots init ----------------
__global__ void k_copy_in(const float* __restrict__ src){
    int i = blockIdx.x * 256 + threadIdx.x;
    g_slots[i] = src[i];
}

// ---------------- initial: s=LN(slots), q=s@q_w (4 rows per block) ----------------
__global__ void __launch_bounds__(256) k_slotlnq(const float* __restrict__ qw,
                                                 const float* __restrict__ lg,
                                                 const float* __restrict__ lb){
    __shared__ float sm[4][256];
    int tid = threadIdx.x, warp = tid >> 5, lane = tid & 31;
    int b = blockIdx.x >> 2, r0 = (blockIdx.x & 3) * 4;
    if (warp < 4) {
        int row = b*16 + r0 + warp;
        float v[8]; float s1 = 0.f;
#pragma unroll
        for (int j = 0; j < 8; j++) { v[j] = g_slots[(size_t)row*256 + lane + 32*j]; s1 += v[j]; }
        s1 = warpSum(s1); float mu = s1 * (1.f/256.f);
        float s2 = 0.f;
#pragma unroll
        for (int j = 0; j < 8; j++) { float dd = v[j] - mu; s2 += dd*dd; }
        s2 = warpSum(s2); float rs = rsqrtf(s2 * (1.f/256.f) + EPSF);
#pragma unroll
        for (int j = 0; j < 8; j++) {
            int d = lane + 32*j;
            float sv = (v[j] - mu) * rs * lg[d] + lb[d];
            sm[warp][d] = sv;
            g_s[(size_t)row*256 + d] = sv;
        }
    }
    __syncthreads();
    float a0=0,a1=0,a2=0,a3=0;
    for (int d = 0; d < 256; d++) {
        float w = qw[(size_t)d*256 + tid];
        a0 += sm[0][d]*w; a1 += sm[1][d]*w; a2 += sm[2][d]*w; a3 += sm[3][d]*w;
    }
    int base = (b*16 + r0) * 256;
    g_q[base       + tid] = a0;
    g_q[base + 256 + tid] = a1;
    g_q[base + 512 + tid] = a2;
    g_q[base + 768 + tid] = a3;
}

// ---------------- logits + softmax(over slots) + partial upd ----------------
__global__ void __launch_bounds__(256) k_attn(){
    __shared__ __align__(16) float qs[16][260];
    __shared__ __align__(16) float ksh[8][260];
    __shared__ float attn_s[64][16];
    int tid = threadIdx.x;
    int chunk = blockIdx.x, b = blockIdx.y;
#pragma unroll
    for (int i = 0; i < 16; i++) qs[i][tid] = g_q[(size_t)(b*NSLOT + i)*DD + tid];
    __syncthreads();
    int warp = tid >> 5, lane = tid & 31;
    for (int step = 0; step < 8; step++) {
        int nl = step*8 + warp;
        const float* kr = g_k + ((size_t)(b*NSAMP + chunk*64 + nl))*DD;
#pragma unroll
        for (int j = 0; j < 8; j++) ksh[warp][lane + 32*j] = kr[lane + 32*j];
        __syncwarp();
        float logit = -1e30f;
        if (lane < 16) {
            float a = 0.f;
#pragma unroll 8
            for (int d = 0; d < 256; d += 4) {
                float4 qv = *(const float4*)&qs[lane][d];
                float4 kv = *(const float4*)&ksh[warp][d];
                a += qv.x*kv.x + qv.y*kv.y + qv.z*kv.z + qv.w*kv.w;
            }
            logit = a * 0.0625f;           // D^-0.5
        }
        float m = logit;
#pragma unroll
        for (int o = 8; o > 0; o >>= 1) m = fmaxf(m, __shfl_xor_sync(0xffffffffu, m, o));
        float e = expf(logit - m);
        float ss = e;
#pragma unroll
        for (int o = 8; o > 0; o >>= 1) ss += __shfl_xor_sync(0xffffffffu, ss, o);
        if (lane < 16) attn_s[nl][lane] = e / ss;
        __syncwarp();
    }
    __syncthreads();
    float acc[16];
#pragma unroll
    for (int kk = 0; kk < 16; kk++) acc[kk] = 0.f;
    for (int nl = 0; nl < 64; nl++) {
        float vv = g_v[((size_t)(b*NSAMP + chunk*64 + nl))*DD + tid];
#pragma unroll
        for (int kk = 0; kk < 16; kk++) acc[kk] += attn_s[nl][kk] * vv;
    }
#pragma unroll
    for (int kk = 0; kk < 16; kk++)
        g_updpart[((size_t)(b*8 + chunk))*(NSLOT*DD) + kk*DD + tid] = acc[kk];
}

// ---------------- reduce partials + LN + MLP + slot update + next-iter LN/q (fused) ----------------
__global__ void __launch_bounds__(512) k_updmlp(const float* __restrict__ lmg, const float* __restrict__ lmb,
                                                const float* __restrict__ w1,  const float* __restrict__ b1,
                                                const float* __restrict__ w2,  const float* __restrict__ b2,
                                                const float* __restrict__ qw,
                                                const float* __restrict__ lsg, const float* __restrict__ lsb){
    __shared__ float usm[4][256];
    __shared__ float hsm[4][256];
    __shared__ float gsm[4][512];
    int tid = threadIdx.x;
    int b = blockIdx.x >> 2, r0 = (blockIdx.x & 3) * 4;
    for (int idx = tid; idx < 1024; idx += 512) {
        int row = idx >> 8, d = idx & 255;
        float u = 0.f;
#pragma unroll
        for (int c = 0; c < 8; c++)
            u += g_updpart[((size_t)(b*8 + c))*(NSLOT*DD) + (size_t)(r0 + row)*DD + d];
        usm[row][d] = u;
    }
    __syncthreads();
    int warp = tid >> 5, lane = tid & 31;
    if (warp < 4) {
        float v[8]; float s1 = 0.f;
#pragma unroll
        for (int j = 0; j < 8; j++) { v[j] = usm[warp][lane + 32*j]; s1 += v[j]; }
        s1 = warpSum(s1); float mu = s1 * (1.f/256.f);
        float s2 = 0.f;
#pragma unroll
        for (int j = 0; j < 8; j++) { float dd = v[j] - mu; s2 += dd*dd; }
        s2 = warpSum(s2); float rs = rsqrtf(s2 * (1.f/256.f) + EPSF);
#pragma unroll
        for (int j = 0; j < 8; j++) {
            int d = lane + 32*j;
            hsm[warp][d] = (v[j] - mu) * rs * lmg[d] + lmb[d];
        }
    }
    __syncthreads();
    float a0 = b1[tid], a1 = a0, a2 = a0, a3 = a0;
    for (int d = 0; d < 256; d++) {
        float w = w1[(size_t)d*512 + tid];
        a0 += hsm[0][d]*w; a1 += hsm[1][d]*w; a2 += hsm[2][d]*w; a3 += hsm[3][d]*w;
    }
    gsm[0][tid] = geluf(a0); gsm[1][tid] = geluf(a1);
    gsm[2][tid] = geluf(a2); gsm[3][tid] = geluf(a3);
    __syncthreads();
    int base = (b*16 + r0) * 256;
    if (tid < 256) {
        float m0=0,m1=0,m2=0,m3=0;
        for (int j = 0; j < 512; j++) {
            float w = w2[(size_t)j*256 + tid];
            m0 += gsm[0][j]*w; m1 += gsm[1][j]*w; m2 += gsm[2][j]*w; m3 += gsm[3][j]*w;
        }
        float bb = b2[tid];
        float n0 = g_s[base       + tid] + m0 + bb;
        float n1 = g_s[base + 256 + tid] + m1 + bb;
        float n2 = g_s[base + 512 + tid] + m2 + bb;
        float n3 = g_s[base + 768 + tid] + m3 + bb;
        g_slots[base       + tid] = n0;
        g_slots[base + 256 + tid] = n1;
        g_slots[base + 512 + tid] = n2;
        g_slots[base + 768 + tid] = n3;
        usm[0][tid] = n0; usm[1][tid] = n1; usm[2][tid] = n2; usm[3][tid] = n3;
    }
    __syncthreads();
    // ---- next iteration's s = LN(slots) and q = s @ q_w (fused epilogue) ----
    if (warp < 4) {
        float v[8]; float s1 = 0.f;
#pragma unroll
        for (int j = 0; j < 8; j++) { v[j] = usm[warp][lane + 32*j]; s1 += v[j]; }
        s1 = warpSum(s1); float mu = s1 * (1.f/256.f);
        float s2 = 0.f;
#pragma unroll
        for (int j = 0; j < 8; j++) { float dd = v[j] - mu; s2 += dd*dd; }
        s2 = warpSum(s2); float rs = rsqrtf(s2 * (1.f/256.f) + EPSF);
#pragma unroll
        for (int j = 0; j < 8; j++) {
            int d = lane + 32*j;
            float sv = (v[j] - mu) * rs * lsg[d] + lsb[d];
            hsm[warp][d] = sv;
            g_s[(size_t)(b*16 + r0 + warp)*256 + d] = sv;
        }
    }
    __syncthreads();
    if (tid < 256) {
        float q0=0,q1=0,q2=0,q3=0;
        for (int d = 0; d < 256; d++) {
            float w = qw[(size_t)d*256 + tid];
            q0 += hsm[0][d]*w; q1 += hsm[1][d]*w; q2 += hsm[2][d]*w; q3 += hsm[3][d]*w;
        }
        g_q[base       + tid] = q0;
        g_q[base + 256 + tid] = q1;
        g_q[base + 512 + tid] = q2;
        g_q[base + 768 + tid] = q3;
    }
}

// ---------------- decoder stage 1+2 (4 rows / block) ----------------
__global__ void __launch_bounds__(512) k_dec1(const float* __restrict__ w1, const float* __restrict__ b1,
                                              const float* __restrict__ w2, const float* __restrict__ b2){
    __shared__ float ssm[4][256];
    __shared__ float g1[4][512];
    int tid = threadIdx.x;
    int r0 = blockIdx.x * 4;
    for (int idx = tid; idx < 1024; idx += 512)
        ssm[idx >> 8][idx & 255] = g_slots[(size_t)(r0 + (idx >> 8))*256 + (idx & 255)];
    __syncthreads();
    float a0 = b1[tid], a1 = a0, a2 = a0, a3 = a0;
    for (int d = 0; d < 256; d++) {
        float w = w1[(size_t)d*512 + tid];
        a0 += ssm[0][d]*w; a1 += ssm[1][d]*w; a2 += ssm[2][d]*w; a3 += ssm[3][d]*w;
    }
    g1[0][tid] = geluf(a0); g1[1][tid] = geluf(a1);
    g1[2][tid] = geluf(a2); g1[3][tid] = geluf(a3);
    __syncthreads();
    float c0 = b2[tid], c1 = c0, c2 = c0, c3 = c0;
    for (int j = 0; j < 512; j++) {
        float w = w2[(size_t)j*512 + tid];
        c0 += g1[0][j]*w; c1 += g1[1][j]*w; c2 += g1[2][j]*w; c3 += g1[3][j]*w;
    }
    g_r2[(size_t)(r0+0)*512 + tid] = geluf(c0);
    g_r2[(size_t)(r0+1)*512 + tid] = geluf(c1);
    g_r2[(size_t)(r0+2)*512 + tid] = geluf(c2);
    g_r2[(size_t)(r0+3)*512 + tid] = geluf(c3);
}

__global__ void k_rbar(){
    int gi = blockIdx.x * 256 + threadIdx.x;   // 4096 = 8 * 512
    int b = gi >> 9, j = gi & 511;
    float s = 0.f;
#pragma unroll
    for (int kk = 0; kk < 16; kk++) s += g_r2[(size_t)(b*16 + kk)*512 + j];
    g_rbar[gi] = s * (1.f/16.f);
}

__global__ void __launch_bounds__(128) k_recon(const float* __restrict__ w3, const float* __restrict__ b3){
    __shared__ float rb[8][512];
    int tid = threadIdx.x;
    for (int idx = tid; idx < 4096; idx += 128) rb[idx >> 9][idx & 511] = g_rbar[idx];
    __syncthreads();
    int h = blockIdx.x * 128 + tid;
    float bv = b3[h];
    float acc[8];
#pragma unroll
    for (int b = 0; b < 8; b++) acc[b] = bv;
    for (int j = 0; j < 512; j++) {
        float w = w3[(size_t)j*HID + h];
#pragma unroll
        for (int b = 0; b < 8; b++) acc[b] += rb[b][j] * w;
    }
#pragma unroll
    for (int b = 0; b < 8; b++) g_recon[(size_t)b*HID + h] = acc[b];
}

__global__ void __launch_bounds__(1024) k_loss(float* __restrict__ out, int out_size){
    __shared__ float buf[1024];
    int tid = threadIdx.x;
    float s = 0.f;
    for (int i = tid; i < NB*HID; i += 1024) {
        float dd = g_recon[i] - g_target[i];
        s += dd * dd;
    }
    buf[tid] = s; __syncthreads();
    for (int st = 512; st > 0; st >>= 1) { if (tid < st) buf[tid] += buf[tid + st]; __syncthreads(); }
    if (tid == 0) out[out_size - 1] = buf[0] * (1.f / (float)(NB*HID));
}

__global__ void k_copy_out(float* __restrict__ out, int out_size){
    int i = blockIdx.x * 256 + threadIdx.x;
    if (i < NB*NSLOT*DD && i < out_size) out[i] = g_slots[i];
}

// ---------------- launcher ----------------
extern "C" void kernel_launch(void* const* d_in, const int* in_sizes, int n_in,
                              void* d_out, int out_size){
    const float* hs        = (const float*)d_in[0];
    const float* old_slots = (const float*)d_in[1];
    const float* in_w      = (const float*)d_in[2];
    const float* in_b      = (const float*)d_in[3];
    const float* ln_in_g   = (const float*)d_in[4];
    const float* ln_in_b   = (const float*)d_in[5];
    const float* ln_s_g    = (const float*)d_in[6];
    const float* ln_s_b    = (const float*)d_in[7];
    const float* ln_m_g    = (const float*)d_in[8];
    const float* ln_m_b    = (const float*)d_in[9];
    const float* q_w       = (const float*)d_in[10];
    const float* k_w       = (const float*)d_in[11];
    const float* v_w       = (const float*)d_in[12];
    const float* mlp_w1    = (const float*)d_in[13];
    const float* mlp_b1    = (const float*)d_in[14];
    const float* mlp_w2    = (const float*)d_in[15];
    const float* mlp_b2    = (const float*)d_in[16];
    const float* dec_w1    = (const float*)d_in[17];
    const float* dec_b1    = (const float*)d_in[18];
    const float* dec_w2    = (const float*)d_in[19];
    const float* dec_b2    = (const float*)d_in[20];
    const float* dec_w3    = (const float*)d_in[21];
    const float* dec_b3    = (const float*)d_in[22];
    float* out = (float*)d_out;

    k_init_idx<<<1, 512>>>();

    // fused front: interleaved gather-GEMM (8x8 microtile, cp.async) + mean partials
    k_front<<<1024, 256>>>(hs, in_w);
    k_redln<<<NB*NSAMP, 256>>>(in_b, ln_in_g, ln_in_b);      // reduce + bias + LN -> g_x
    k_mean_reduce<<<128, 256>>>();
    k_gemmkv<<<dim3(4, 64, 2), 256>>>(k_w, v_w);             // k and v in one launch

    k_copy_in<<<128, 256>>>(old_slots);
    k_slotlnq<<<32, 256>>>(q_w, ln_s_g, ln_s_b);             // initial s, q
    for (int it = 0; it < 3; it++) {
        k_attn<<<dim3(8, 8), 256>>>();
        k_updmlp<<<32, 512>>>(ln_m_g, ln_m_b, mlp_w1, mlp_b1, mlp_w2, mlp_b2,
                              q_w, ln_s_g, ln_s_b);          // + next-iter LN/q fused
    }

    k_dec1<<<32, 512>>>(dec_w1, dec_b1, dec_w2, dec_b2);
    k_rbar<<<16, 256>>>();
    k_recon<<<32, 128>>>(dec_w3, dec_b3);
    k_loss<<<1, 1024>>>(out, out_size);
    k_copy_out<<<128, 256>>>(out, out_size);
}

// round 15
// speedup vs baseline: 1.5764x; 1.0559x over previous
#include <cuda_runtime.h>
#include <cuda_bf16.h>
#include <math.h>

#define NB     8
#define TT     4096
#define HID    4096
#define NSAMP  512
#define NSLOT  16
#define DD     256
#define BOTD   512
#define EPSF   1e-5f
#define KSPLIT 8
#define KCHUNK 512   // HID / KSPLIT
#define NSLICE (KCHUNK/16)

typedef unsigned int u32;

// ---------------- scratch (no allocations allowed) ----------------
__device__ float g_gpart  [KSPLIT*NB*NSAMP*DD];   // K-split partials
__device__ float g_x      [NB*NSAMP*DD];
__device__ float g_k      [NB*NSAMP*DD];
__device__ float g_v      [NB*NSAMP*DD];
__device__ int   g_idx    [NSAMP];
__device__ float g_tpart  [32*NB*HID];
__device__ float g_target [NB*HID];
__device__ float g_slots  [NB*NSLOT*DD];
__device__ float g_s      [NB*NSLOT*DD];
__device__ float g_q      [NB*NSLOT*DD];
__device__ float g_updpart[NB*8*NSLOT*DD];   // (b,chunk,k,d)
__device__ float g_r2     [NB*NSLOT*BOTD];
__device__ float g_rbar   [NB*BOTD];
__device__ float g_recon  [NB*HID];

// ---------------- helpers ----------------
__device__ __forceinline__ float warpSum(float v){
#pragma unroll
    for (int o = 16; o > 0; o >>= 1) v += __shfl_xor_sync(0xffffffffu, v, o);
    return v;
}
__device__ __forceinline__ float geluf(float x){
    return 0.5f * x * (1.0f + erff(x * 0.7071067811865475f));
}
__device__ __forceinline__ u32 smem_u32(const void* p){
    return (u32)__cvta_generic_to_shared(p);
}
__device__ __forceinline__ u32 packbf2(float x0, float x1){
    __nv_bfloat162 p = __floats2bfloat162_rn(x0, x1);   // (x, y) = (x0, x1), x0 low
    return *(u32*)&p;
}
__device__ __forceinline__ void ldsm4(u32& r0, u32& r1, u32& r2, u32& r3, u32 addr){
    asm volatile("ldmatrix.sync.aligned.m8n8.x4.shared.b16 {%0,%1,%2,%3},[%4];\n"
        : "=r"(r0), "=r"(r1), "=r"(r2), "=r"(r3) : "r"(addr));
}
__device__ __forceinline__ void ldsm2t(u32& r0, u32& r1, u32 addr){
    asm volatile("ldmatrix.sync.aligned.m8n8.x2.trans.shared.b16 {%0,%1},[%2];\n"
        : "=r"(r0), "=r"(r1) : "r"(addr));
}
__device__ __forceinline__ void mma16816(float* c, const u32* a, const u32* b){
    asm volatile(
        "mma.sync.aligned.m16n8k16.row.col.f32.bf16.bf16.f32 "
        "{%0,%1,%2,%3},{%4,%5,%6,%7},{%8,%9},{%0,%1,%2,%3};\n"
        : "+f"(c[0]), "+f"(c[1]), "+f"(c[2]), "+f"(c[3])
        : "r"(a[0]), "r"(a[1]), "r"(a[2]), "r"(a[3]), "r"(b[0]), "r"(b[1]));
}

// ---------------- idx = concat(linspace(0,T-256,256).astype(i32), arange(T-256,T)) ----------------
__global__ void k_init_idx(){
    int i = threadIdx.x;
    if (i < 256) {
        const float delta = 3840.0f / 255.0f;     // fp32, matches jnp.linspace step
        g_idx[i] = (int)((float)i * delta);       // truncation == astype(int32)
    } else {
        g_idx[i] = 3840 + (i - 256);
    }
}

// ===========================================================================
// k_front: 2048 blocks of 256 threads, 2 blocks/SM.
//   odd  blocks (1024): mean partial sums (DRAM-bound)
//   even blocks (1024): K-split gather GEMM on TENSOR CORES:
//       bf16 hi/lo split (xh@Wh + xh@Wl + xl@Wh), 128x64 tile, K-chunk 512,
//       mma.sync.m16n8k16 + ldmatrix, double-buffered smem.
// ===========================================================================
#define A_STR 24   // bf16 elems per A smem row (16 data + 8 pad), 48B
#define B_STR 72   // bf16 elems per B smem row (64 data + 8 pad), 144B

__global__ void __launch_bounds__(256, 2) k_front(const float* __restrict__ hs,
                                                  const float* __restrict__ Bw){
    __shared__ __align__(16) __nv_bfloat16 sAh[2][128*A_STR];
    __shared__ __align__(16) __nv_bfloat16 sAl[2][128*A_STR];
    __shared__ __align__(16) __nv_bfloat16 sBh[2][16*B_STR];
    __shared__ __align__(16) __nv_bfloat16 sBl[2][16*B_STR];

    int bid = blockIdx.x;
    int tid = threadIdx.x;

    if (bid & 1) {
        // ---------------- mean partial: 128 t-steps x 1024 h ----------------
        int mid = bid >> 1;                 // 0..1023
        int hb = (mid & 3) * 1024 + tid * 4;
        int b  = (mid >> 2) & 7;
        int c  = mid >> 5;                  // 0..31
        const float* p = hs + ((size_t)b*TT + (size_t)c*128)*HID + hb;
        float4 acc0 = make_float4(0,0,0,0), acc1 = make_float4(0,0,0,0);
#pragma unroll 4
        for (int t = 0; t < 128; t += 2) {
            float4 v0 = *(const float4*)(p + (size_t)t*HID);
            float4 v1 = *(const float4*)(p + (size_t)(t+1)*HID);
            acc0.x += v0.x; acc0.y += v0.y; acc0.z += v0.z; acc0.w += v0.w;
            acc1.x += v1.x; acc1.y += v1.y; acc1.z += v1.z; acc1.w += v1.w;
        }
        float4 acc = make_float4(acc0.x+acc1.x, acc0.y+acc1.y, acc0.z+acc1.z, acc0.w+acc1.w);
        *(float4*)&g_tpart[((size_t)c*NB + b)*HID + hb] = acc;
        return;
    }

    // ---------------- tensor-core gather GEMM block ----------------
    int gid  = bid >> 1;                    // 0..1023
    int ct   = gid & 3;                     // col tile (64 wide)
    int rt   = (gid >> 2) & 31;             // row tile (128 rows)
    int ks   = gid >> 7;                    // K-split 0..7
    int bcol = ct * 64;
    int brow = rt * 128;

    // ----- global load setup -----
    // A: thread t loads 8 fp32 of gathered row (t>>1), half (t&1)
    int ar = tid >> 1, ah = tid & 1;
    int rg = brow + ar;
    const float* gA = hs + ((size_t)((rg >> 9)*TT + g_idx[rg & 511]))*HID
                         + ks*KCHUNK + ah*8;
    // B: thread t loads 4 fp32 of in_w row (t>>4), cols (t&15)*4
    int bk = tid >> 4, bc = (tid & 15) * 4;
    const float* gB = Bw + ((size_t)(ks*KCHUNK + bk))*256 + bcol + bc;

    // smem store addresses
    __nv_bfloat16* aDstH[2] = { &sAh[0][ar*A_STR + ah*8], &sAh[1][ar*A_STR + ah*8] };
    __nv_bfloat16* aDstL[2] = { &sAl[0][ar*A_STR + ah*8], &sAl[1][ar*A_STR + ah*8] };
    __nv_bfloat16* bDstH[2] = { &sBh[0][bk*B_STR + bc],   &sBh[1][bk*B_STR + bc] };
    __nv_bfloat16* bDstL[2] = { &sBl[0][bk*B_STR + bc],   &sBl[1][bk*B_STR + bc] };

    // ----- mma setup -----
    int warp = tid >> 5, lane = tid & 31;
    int wm = warp >> 2;          // 0..1 : 64-row half
    int wn = warp & 3;           // 0..3 : 16-col strip
    // ldmatrix lane offsets
    int aRowL = (lane & 7) + ((lane >> 3) & 1) * 8;     // 0..15
    int aKoff = (lane >> 4) * 8;                        // 0 or 8
    u32 aOffLane = (u32)((aRowL*A_STR + aKoff) * 2);
    u32 bOffLane = (u32)(((lane & 15)*B_STR) * 2);
    u32 aBaseH[2] = { smem_u32(&sAh[0][0]), smem_u32(&sAh[1][0]) };
    u32 aBaseL[2] = { smem_u32(&sAl[0][0]), smem_u32(&sAl[1][0]) };
    u32 bBaseH[2] = { smem_u32(&sBh[0][0]), smem_u32(&sBh[1][0]) };
    u32 bBaseL[2] = { smem_u32(&sBl[0][0]), smem_u32(&sBl[1][0]) };

    float acc[4][2][4];
#pragma unroll
    for (int i = 0; i < 4; i++)
#pragma unroll
        for (int j = 0; j < 2; j++)
#pragma unroll
            for (int r = 0; r < 4; r++) acc[i][j][r] = 0.f;

    float apf[8]; float bpf[4];

    // prologue: load slice 0
    {
        float4 a0 = *(const float4*)(gA);
        float4 a1 = *(const float4*)(gA + 4);
        apf[0]=a0.x; apf[1]=a0.y; apf[2]=a0.z; apf[3]=a0.w;
        apf[4]=a1.x; apf[5]=a1.y; apf[6]=a1.z; apf[7]=a1.w;
        float4 b0 = *(const float4*)(gB);
        bpf[0]=b0.x; bpf[1]=b0.y; bpf[2]=b0.z; bpf[3]=b0.w;
    }
    // convert + store slice 0 -> buf 0
    {
        u32 h[4], l[4];
#pragma unroll
        for (int j = 0; j < 4; j++) {
            float x0 = apf[2*j], x1 = apf[2*j+1];
            __nv_bfloat16 h0 = __float2bfloat16(x0), h1 = __float2bfloat16(x1);
            float l0 = x0 - __bfloat162float(h0), l1 = x1 - __bfloat162float(h1);
            h[j] = packbf2(__bfloat162float(h0), __bfloat162float(h1));
            l[j] = packbf2(l0, l1);
        }
        *(uint4*)aDstH[0] = make_uint4(h[0],h[1],h[2],h[3]);
        *(uint4*)aDstL[0] = make_uint4(l[0],l[1],l[2],l[3]);
        u32 bh[2], bl[2];
#pragma unroll
        for (int j = 0; j < 2; j++) {
            float x0 = bpf[2*j], x1 = bpf[2*j+1];
            __nv_bfloat16 h0 = __float2bfloat16(x0), h1 = __float2bfloat16(x1);
            float l0 = x0 - __bfloat162float(h0), l1 = x1 - __bfloat162float(h1);
            bh[j] = packbf2(__bfloat162float(h0), __bfloat162float(h1));
            bl[j] = packbf2(l0, l1);
        }
        *(uint2*)bDstH[0] = make_uint2(bh[0], bh[1]);
        *(uint2*)bDstL[0] = make_uint2(bl[0], bl[1]);
    }
    // prefetch slice 1
    if (NSLICE > 1) {
        float4 a0 = *(const float4*)(gA + 16);
        float4 a1 = *(const float4*)(gA + 20);
        apf[0]=a0.x; apf[1]=a0.y; apf[2]=a0.z; apf[3]=a0.w;
        apf[4]=a1.x; apf[5]=a1.y; apf[6]=a1.z; apf[7]=a1.w;
        float4 b0 = *(const float4*)(gB + (size_t)16*256);
        bpf[0]=b0.x; bpf[1]=b0.y; bpf[2]=b0.z; bpf[3]=b0.w;
    }
    __syncthreads();

    int buf = 0;
#pragma unroll 1
    for (int s = 0; s < NSLICE; s++) {
        // ---- mma on buf ----
        u32 af[2][4][4];
#pragma unroll
        for (int mf = 0; mf < 4; mf++) {
            u32 ao = (u32)((wm*64 + mf*16)*A_STR*2) + aOffLane;
            ldsm4(af[0][mf][0], af[0][mf][1], af[0][mf][2], af[0][mf][3], aBaseH[buf] + ao);
            ldsm4(af[1][mf][0], af[1][mf][1], af[1][mf][2], af[1][mf][3], aBaseL[buf] + ao);
        }
        u32 bfr[2][2][2];
#pragma unroll
        for (int nf = 0; nf < 2; nf++) {
            u32 bo = bOffLane + (u32)((wn*16 + nf*8)*2);
            ldsm2t(bfr[0][nf][0], bfr[0][nf][1], bBaseH[buf] + bo);
            ldsm2t(bfr[1][nf][0], bfr[1][nf][1], bBaseL[buf] + bo);
        }
#pragma unroll
        for (int mf = 0; mf < 4; mf++) {
#pragma unroll
            for (int nf = 0; nf < 2; nf++) {
                mma16816(acc[mf][nf], af[0][mf], bfr[0][nf]);   // hi @ hi
                mma16816(acc[mf][nf], af[0][mf], bfr[1][nf]);   // hi @ lo
                mma16816(acc[mf][nf], af[1][mf], bfr[0][nf]);   // lo @ hi
            }
        }
        // ---- stage slice s+1 into buf^1, prefetch s+2 ----
        if (s < NSLICE - 1) {
            int nb = buf ^ 1;
            u32 h[4], l[4];
#pragma unroll
            for (int j = 0; j < 4; j++) {
                float x0 = apf[2*j], x1 = apf[2*j+1];
                __nv_bfloat16 h0 = __float2bfloat16(x0), h1 = __float2bfloat16(x1);
                float l0 = x0 - __bfloat162float(h0), l1 = x1 - __bfloat162float(h1);
                h[j] = packbf2(__bfloat162float(h0), __bfloat162float(h1));
                l[j] = packbf2(l0, l1);
            }
            *(uint4*)aDstH[nb] = make_uint4(h[0],h[1],h[2],h[3]);
            *(uint4*)aDstL[nb] = make_uint4(l[0],l[1],l[2],l[3]);
            u32 bh[2], bl[2];
#pragma unroll
            for (int j = 0; j < 2; j++) {
                float x0 = bpf[2*j], x1 = bpf[2*j+1];
                __nv_bfloat16 h0 = __float2bfloat16(x0), h1 = __float2bfloat16(x1);
                float l0 = x0 - __bfloat162float(h0), l1 = x1 - __bfloat162float(h1);
                bh[j] = packbf2(__bfloat162float(h0), __bfloat162float(h1));
                bl[j] = packbf2(l0, l1);
            }
            *(uint2*)bDstH[nb] = make_uint2(bh[0], bh[1]);
            *(uint2*)bDstL[nb] = make_uint2(bl[0], bl[1]);
            if (s < NSLICE - 2) {
                int ko = (s + 2) * 16;
                float4 a0 = *(const float4*)(gA + ko);
                float4 a1 = *(const float4*)(gA + ko + 4);
                apf[0]=a0.x; apf[1]=a0.y; apf[2]=a0.z; apf[3]=a0.w;
                apf[4]=a1.x; apf[5]=a1.y; apf[6]=a1.z; apf[7]=a1.w;
                float4 b0 = *(const float4*)(gB + (size_t)ko*256);
                bpf[0]=b0.x; bpf[1]=b0.y; bpf[2]=b0.z; bpf[3]=b0.w;
            }
            __syncthreads();
            buf = nb;
        }
    }

    // ---- epilogue: write fp32 partials ----
    float* C = g_gpart + (size_t)ks*(NB*NSAMP*DD);
    int cr = lane >> 2, cc = (lane & 3) * 2;
#pragma unroll
    for (int mf = 0; mf < 4; mf++) {
#pragma unroll
        for (int nf = 0; nf < 2; nf++) {
            int row0 = brow + wm*64 + mf*16 + cr;
            int col  = bcol + wn*16 + nf*8 + cc;
            *(float2*)&C[(size_t)row0*256 + col]       = make_float2(acc[mf][nf][0], acc[mf][nf][1]);
            *(float2*)&C[(size_t)(row0+8)*256 + col]   = make_float2(acc[mf][nf][2], acc[mf][nf][3]);
        }
    }
}

__global__ void k_mean_reduce(){
    int gi = blockIdx.x * 256 + threadIdx.x;   // gi = b*HID + h, 32768 total
    float s = 0.f;
#pragma unroll
    for (int c = 0; c < 32; c++) s += g_tpart[(size_t)c*NB*HID + gi];
    g_target[gi] = s * (1.0f / (float)TT);
}

// ---------------- reduce K-split partials + bias + LayerNorm -> g_x (fused) ----------------
__global__ void __launch_bounds__(256) k_redln(const float* __restrict__ bias,
                                               const float* __restrict__ gg,
                                               const float* __restrict__ bb){
    __shared__ float buf[256];
    int r = blockIdx.x, tid = threadIdx.x;
    float v = bias[tid];
#pragma unroll
    for (int s = 0; s < KSPLIT; s++)
        v += g_gpart[(size_t)s*(NB*NSAMP*DD) + (size_t)r*256 + tid];
    buf[tid] = v; __syncthreads();
    for (int s = 128; s > 0; s >>= 1) { if (tid < s) buf[tid] += buf[tid + s]; __syncthreads(); }
    float mu = buf[0] * (1.f/256.f); __syncthreads();
    float d = v - mu;
    buf[tid] = d * d; __syncthreads();
    for (int s = 128; s > 0; s >>= 1) { if (tid < s) buf[tid] += buf[tid + s]; __syncthreads(); }
    float var = buf[0] * (1.f/256.f);
    g_x[(size_t)r*256 + tid] = d * rsqrtf(var + EPSF) * gg[tid] + bb[tid];
}

// ---------------- k/v projections in one launch: grid (4, 64, 2), K=256, double-buffered ----------------
__global__ void __launch_bounds__(256) k_gemmkv(const float* __restrict__ kw,
                                                const float* __restrict__ vw){
    __shared__ __align__(16) float As[2][16][64];
    __shared__ __align__(16) float Bs[2][16][64];
    int tid  = threadIdx.x;
    int bcol = blockIdx.x * 64, brow = blockIdx.y * 64;
    const float* Bw = blockIdx.z ? vw : kw;
    float* C        = blockIdx.z ? g_v : g_k;
    int arow = tid >> 2, ak = (tid & 3) * 4;
    const float* Arow = g_x + (size_t)(brow + arow) * DD;
    int brr = tid >> 4, bc = (tid & 15) * 4;
    int ty  = tid >> 4, tx = tid & 15;
    float acc[4][4] = {};

    float4 a4 = *(const float4*)(Arow + ak);
    float4 b4 = *(const float4*)(Bw + (size_t)brr*256 + bcol + bc);
    As[0][ak+0][arow] = a4.x; As[0][ak+1][arow] = a4.y;
    As[0][ak+2][arow] = a4.z; As[0][ak+3][arow] = a4.w;
    *(float4*)&Bs[0][brr][bc] = b4;
    __syncthreads();

    int buf = 0;
#pragma unroll 1
    for (int kt = 0; kt < 16; kt++) {
        if (kt < 15) {
            a4 = *(const float4*)(Arow + (kt+1)*16 + ak);
            b4 = *(const float4*)(Bw + (size_t)((kt+1)*16 + brr)*256 + bcol + bc);
        }
#pragma unroll
        for (int kk = 0; kk < 16; kk++) {
            float4 av = *(const float4*)&As[buf][kk][ty*4];
            float4 bv = *(const float4*)&Bs[buf][kk][tx*4];
            acc[0][0]+=av.x*bv.x; acc[0][1]+=av.x*bv.y; acc[0][2]+=av.x*bv.z; acc[0][3]+=av.x*bv.w;
            acc[1][0]+=av.y*bv.x; acc[1][1]+=av.y*bv.y; acc[1][2]+=av.y*bv.z; acc[1][3]+=av.y*bv.w;
            acc[2][0]+=av.z*bv.x; acc[2][1]+=av.z*bv.y; acc[2][2]+=av.z*bv.z; acc[2][3]+=av.z*bv.w;
            acc[3][0]+=av.w*bv.x; acc[3][1]+=av.w*bv.y; acc[3][2]+=av.w*bv.z; acc[3][3]+=av.w*bv.w;
        }
        if (kt < 15) {
            int nb = buf ^ 1;
            As[nb][ak+0][arow] = a4.x; As[nb][ak+1][arow] = a4.y;
            As[nb][ak+2][arow] = a4.z; As[nb][ak+3][arow] = a4.w;
            *(float4*)&Bs[nb][brr][bc] = b4;
            buf = nb;
            __syncthreads();
        }
    }
#pragma unroll
    for (int i = 0; i < 4; i++)
#pragma unroll
        for (int j = 0; j < 4; j++)
            C[(size_t)(brow + ty*4 + i)*256 + bcol + tx*4 + j] = acc[i][j];
}

// ---------------- slots init ----------------
__global__ void k_copy_in(const float* __restrict__ src){
    int i = blockIdx.x * 256 + threadIdx.x;
    g_slots[i] = src[i];
}

// ---------------- initial: s=LN(slots), q=s@q_w (4 rows per block) ----------------
__global__ void __launch_bounds__(256) k_slotlnq(const float* __restrict__ qw,
                                                 const float* __restrict__ lg,
                                                 const float* __restrict__ lb){
    __shared__ float sm[4][256];
    int tid = threadIdx.x, warp = tid >> 5, lane = tid & 31;
    int b = blockIdx.x >> 2, r0 = (blockIdx.x & 3) * 4;
    if (warp < 4) {
        int row = b*16 + r0 + warp;
        float v[8]; float s1 = 0.f;
#pragma unroll
        for (int j = 0; j < 8; j++) { v[j] = g_slots[(size_t)row*256 + lane + 32*j]; s1 += v[j]; }
        s1 = warpSum(s1); float mu = s1 * (1.f/256.f);
        float s2 = 0.f;
#pragma unroll
        for (int j = 0; j < 8; j++) { float dd = v[j] - mu; s2 += dd*dd; }
        s2 = warpSum(s2); float rs = rsqrtf(s2 * (1.f/256.f) + EPSF);
#pragma unroll
        for (int j = 0; j < 8; j++) {
            int d = lane + 32*j;
            float sv = (v[j] - mu) * rs * lg[d] + lb[d];
            sm[warp][d] = sv;
            g_s[(size_t)row*256 + d] = sv;
        }
    }
    __syncthreads();
    float a0=0,a1=0,a2=0,a3=0;
    for (int d = 0; d < 256; d++) {
        float w = qw[(size_t)d*256 + tid];
        a0 += sm[0][d]*w; a1 += sm[1][d]*w; a2 += sm[2][d]*w; a3 += sm[3][d]*w;
    }
    int base = (b*16 + r0) * 256;
    g_q[base       + tid] = a0;
    g_q[base + 256 + tid] = a1;
    g_q[base + 512 + tid] = a2;
    g_q[base + 768 + tid] = a3;
}

// ---------------- logits + softmax(over slots) + partial upd ----------------
__global__ void __launch_bounds__(256) k_attn(){
    __shared__ __align__(16) float qs[16][260];
    __shared__ __align__(16) float ksh[8][260];
    __shared__ float attn_s[64][16];
    int tid = threadIdx.x;
    int chunk = blockIdx.x, b = blockIdx.y;
#pragma unroll
    for (int i = 0; i < 16; i++) qs[i][tid] = g_q[(size_t)(b*NSLOT + i)*DD + tid];
    __syncthreads();
    int warp = tid >> 5, lane = tid & 31;
    for (int step = 0; step < 8; step++) {
        int nl = step*8 + warp;
        const float* kr = g_k + ((size_t)(b*NSAMP + chunk*64 + nl))*DD;
#pragma unroll
        for (int j = 0; j < 8; j++) ksh[warp][lane + 32*j] = kr[lane + 32*j];
        __syncwarp();
        float logit = -1e30f;
        if (lane < 16) {
            float a = 0.f;
#pragma unroll 8
            for (int d = 0; d < 256; d += 4) {
                float4 qv = *(const float4*)&qs[lane][d];
                float4 kv = *(const float4*)&ksh[warp][d];
                a += qv.x*kv.x + qv.y*kv.y + qv.z*kv.z + qv.w*kv.w;
            }
            logit = a * 0.0625f;           // D^-0.5
        }
        float m = logit;
#pragma unroll
        for (int o = 8; o > 0; o >>= 1) m = fmaxf(m, __shfl_xor_sync(0xffffffffu, m, o));
        float e = expf(logit - m);
        float ss = e;
#pragma unroll
        for (int o = 8; o > 0; o >>= 1) ss += __shfl_xor_sync(0xffffffffu, ss, o);
        if (lane < 16) attn_s[nl][lane] = e / ss;
        __syncwarp();
    }
    __syncthreads();
    float acc[16];
#pragma unroll
    for (int kk = 0; kk < 16; kk++) acc[kk] = 0.f;
    for (int nl = 0; nl < 64; nl++) {
        float vv = g_v[((size_t)(b*NSAMP + chunk*64 + nl))*DD + tid];
#pragma unroll
        for (int kk = 0; kk < 16; kk++) acc[kk] += attn_s[nl][kk] * vv;
    }
#pragma unroll
    for (int kk = 0; kk < 16; kk++)
        g_updpart[((size_t)(b*8 + chunk))*(NSLOT*DD) + kk*DD + tid] = acc[kk];
}

// ---------------- reduce partials + LN + MLP + slot update + next-iter LN/q (fused) ----------------
__global__ void __launch_bounds__(512) k_updmlp(const float* __restrict__ lmg, const float* __restrict__ lmb,
                                                const float* __restrict__ w1,  const float* __restrict__ b1,
                                                const float* __restrict__ w2,  const float* __restrict__ b2,
                                                const float* __restrict__ qw,
                                                const float* __restrict__ lsg, const float* __restrict__ lsb){
    __shared__ float usm[4][256];
    __shared__ float hsm[4][256];
    __shared__ float gsm[4][512];
    int tid = threadIdx.x;
    int b = blockIdx.x >> 2, r0 = (blockIdx.x & 3) * 4;
    for (int idx = tid; idx < 1024; idx += 512) {
        int row = idx >> 8, d = idx & 255;
        float u = 0.f;
#pragma unroll
        for (int c = 0; c < 8; c++)
            u += g_updpart[((size_t)(b*8 + c))*(NSLOT*DD) + (size_t)(r0 + row)*DD + d];
        usm[row][d] = u;
    }
    __syncthreads();
    int warp = tid >> 5, lane = tid & 31;
    if (warp < 4) {
        float v[8]; float s1 = 0.f;
#pragma unroll
        for (int j = 0; j < 8; j++) { v[j] = usm[warp][lane + 32*j]; s1 += v[j]; }
        s1 = warpSum(s1); float mu = s1 * (1.f/256.f);
        float s2 = 0.f;
#pragma unroll
        for (int j = 0; j < 8; j++) { float dd = v[j] - mu; s2 += dd*dd; }
        s2 = warpSum(s2); float rs = rsqrtf(s2 * (1.f/256.f) + EPSF);
#pragma unroll
        for (int j = 0; j < 8; j++) {
            int d = lane + 32*j;
            hsm[warp][d] = (v[j] - mu) * rs * lmg[d] + lmb[d];
        }
    }
    __syncthreads();
    float a0 = b1[tid], a1 = a0, a2 = a0, a3 = a0;
    for (int d = 0; d < 256; d++) {
        float w = w1[(size_t)d*512 + tid];
        a0 += hsm[0][d]*w; a1 += hsm[1][d]*w; a2 += hsm[2][d]*w; a3 += hsm[3][d]*w;
    }
    gsm[0][tid] = geluf(a0); gsm[1][tid] = geluf(a1);
    gsm[2][tid] = geluf(a2); gsm[3][tid] = geluf(a3);
    __syncthreads();
    int base = (b*16 + r0) * 256;
    if (tid < 256) {
        float m0=0,m1=0,m2=0,m3=0;
        for (int j = 0; j < 512; j++) {
            float w = w2[(size_t)j*256 + tid];
            m0 += gsm[0][j]*w; m1 += gsm[1][j]*w; m2 += gsm[2][j]*w; m3 += gsm[3][j]*w;
        }
        float bb = b2[tid];
        float n0 = g_s[base       + tid] + m0 + bb;
        float n1 = g_s[base + 256 + tid] + m1 + bb;
        float n2 = g_s[base + 512 + tid] + m2 + bb;
        float n3 = g_s[base + 768 + tid] + m3 + bb;
        g_slots[base       + tid] = n0;
        g_slots[base + 256 + tid] = n1;
        g_slots[base + 512 + tid] = n2;
        g_slots[base + 768 + tid] = n3;
        usm[0][tid] = n0; usm[1][tid] = n1; usm[2][tid] = n2; usm[3][tid] = n3;
    }
    __syncthreads();
    // ---- next iteration's s = LN(slots) and q = s @ q_w (fused epilogue) ----
    if (warp < 4) {
        float v[8]; float s1 = 0.f;
#pragma unroll
        for (int j = 0; j < 8; j++) { v[j] = usm[warp][lane + 32*j]; s1 += v[j]; }
        s1 = warpSum(s1); float mu = s1 * (1.f/256.f);
        float s2 = 0.f;
#pragma unroll
        for (int j = 0; j < 8; j++) { float dd = v[j] - mu; s2 += dd*dd; }
        s2 = warpSum(s2); float rs = rsqrtf(s2 * (1.f/256.f) + EPSF);
#pragma unroll
        for (int j = 0; j < 8; j++) {
            int d = lane + 32*j;
            float sv = (v[j] - mu) * rs * lsg[d] + lsb[d];
            hsm[warp][d] = sv;
            g_s[(size_t)(b*16 + r0 + warp)*256 + d] = sv;
        }
    }
    __syncthreads();
    if (tid < 256) {
        float q0=0,q1=0,q2=0,q3=0;
        for (int d = 0; d < 256; d++) {
            float w = qw[(size_t)d*256 + tid];
            q0 += hsm[0][d]*w; q1 += hsm[1][d]*w; q2 += hsm[2][d]*w; q3 += hsm[3][d]*w;
        }
        g_q[base       + tid] = q0;
        g_q[base + 256 + tid] = q1;
        g_q[base + 512 + tid] = q2;
        g_q[base + 768 + tid] = q3;
    }
}

// ---------------- decoder stage 1+2 (4 rows / block) ----------------
__global__ void __launch_bounds__(512) k_dec1(const float* __restrict__ w1, const float* __restrict__ b1,
                                              const float* __restrict__ w2, const float* __restrict__ b2){
    __shared__ float ssm[4][256];
    __shared__ float g1[4][512];
    int tid = threadIdx.x;
    int r0 = blockIdx.x * 4;
    for (int idx = tid; idx < 1024; idx += 512)
        ssm[idx >> 8][idx & 255] = g_slots[(size_t)(r0 + (idx >> 8))*256 + (idx & 255)];
    __syncthreads();
    float a0 = b1[tid], a1 = a0, a2 = a0, a3 = a0;
    for (int d = 0; d < 256; d++) {
        float w = w1[(size_t)d*512 + tid];
        a0 += ssm[0][d]*w; a1 += ssm[1][d]*w; a2 += ssm[2][d]*w; a3 += ssm[3][d]*w;
    }
    g1[0][tid] = geluf(a0); g1[1][tid] = geluf(a1);
    g1[2][tid] = geluf(a2); g1[3][tid] = geluf(a3);
    __syncthreads();
    float c0 = b2[tid], c1 = c0, c2 = c0, c3 = c0;
    for (int j = 0; j < 512; j++) {
        float w = w2[(size_t)j*512 + tid];
        c0 += g1[0][j]*w; c1 += g1[1][j]*w; c2 += g1[2][j]*w; c3 += g1[3][j]*w;
    }
    g_r2[(size_t)(r0+0)*512 + tid] = geluf(c0);
    g_r2[(size_t)(r0+1)*512 + tid] = geluf(c1);
    g_r2[(size_t)(r0+2)*512 + tid] = geluf(c2);
    g_r2[(size_t)(r0+3)*512 + tid] = geluf(c3);
}

__global__ void k_rbar(){
    int gi = blockIdx.x * 256 + threadIdx.x;   // 4096 = 8 * 512
    int b = gi >> 9, j = gi & 511;
    float s = 0.f;
#pragma unroll
    for (int kk = 0; kk < 16; kk++) s += g_r2[(size_t)(b*16 + kk)*512 + j];
    g_rbar[gi] = s * (1.f/16.f);
}

__global__ void __launch_bounds__(128) k_recon(const float* __restrict__ w3, const float* __restrict__ b3){
    __shared__ float rb[8][512];
    int tid = threadIdx.x;
    for (int idx = tid; idx < 4096; idx += 128) rb[idx >> 9][idx & 511] = g_rbar[idx];
    __syncthreads();
    int h = blockIdx.x * 128 + tid;
    float bv = b3[h];
    float acc[8];
#pragma unroll
    for (int b = 0; b < 8; b++) acc[b] = bv;
    for (int j = 0; j < 512; j++) {
        float w = w3[(size_t)j*HID + h];
#pragma unroll
        for (int b = 0; b < 8; b++) acc[b] += rb[b][j] * w;
    }
#pragma unroll
    for (int b = 0; b < 8; b++) g_recon[(size_t)b*HID + h] = acc[b];
}

__global__ void __launch_bounds__(1024) k_loss(float* __restrict__ out, int out_size){
    __shared__ float buf[1024];
    int tid = threadIdx.x;
    float s = 0.f;
    for (int i = tid; i < NB*HID; i += 1024) {
        float dd = g_recon[i] - g_target[i];
        s += dd * dd;
    }
    buf[tid] = s; __syncthreads();
    for (int st = 512; st > 0; st >>= 1) { if (tid < st) buf[tid] += buf[tid + st]; __syncthreads(); }
    if (tid == 0) out[out_size - 1] = buf[0] * (1.f / (float)(NB*HID));
}

__global__ void k_copy_out(float* __restrict__ out, int out_size){
    int i = blockIdx.x * 256 + threadIdx.x;
    if (i < NB*NSLOT*DD && i < out_size) out[i] = g_slots[i];
}

// ---------------- launcher ----------------
extern "C" void kernel_launch(void* const* d_in, const int* in_sizes, int n_in,
                              void* d_out, int out_size){
    const float* hs        = (const float*)d_in[0];
    const float* old_slots = (const float*)d_in[1];
    const float* in_w      = (const float*)d_in[2];
    const float* in_b      = (const float*)d_in[3];
    const float* ln_in_g   = (const float*)d_in[4];
    const float* ln_in_b   = (const float*)d_in[5];
    const float* ln_s_g    = (const float*)d_in[6];
    const float* ln_s_b    = (const float*)d_in[7];
    const float* ln_m_g    = (const float*)d_in[8];
    const float* ln_m_b    = (const float*)d_in[9];
    const float* q_w       = (const float*)d_in[10];
    const float* k_w       = (const float*)d_in[11];
    const float* v_w       = (const float*)d_in[12];
    const float* mlp_w1    = (const float*)d_in[13];
    const float* mlp_b1    = (const float*)d_in[14];
    const float* mlp_w2    = (const float*)d_in[15];
    const float* mlp_b2    = (const float*)d_in[16];
    const float* dec_w1    = (const float*)d_in[17];
    const float* dec_b1    = (const float*)d_in[18];
    const float* dec_w2    = (const float*)d_in[19];
    const float* dec_b2    = (const float*)d_in[20];
    const float* dec_w3    = (const float*)d_in[21];
    const float* dec_b3    = (const float*)d_in[22];
    float* out = (float*)d_out;

    k_init_idx<<<1, 512>>>();

    // fused front: interleaved TENSOR-CORE gather-GEMM (bf16 hi/lo split) + mean partials
    k_front<<<2048, 256>>>(hs, in_w);
    k_redln<<<NB*NSAMP, 256>>>(in_b, ln_in_g, ln_in_b);      // reduce + bias + LN -> g_x
    k_mean_reduce<<<128, 256>>>();
    k_gemmkv<<<dim3(4, 64, 2), 256>>>(k_w, v_w);             // k and v in one launch

    k_copy_in<<<128, 256>>>(old_slots);
    k_slotlnq<<<32, 256>>>(q_w, ln_s_g, ln_s_b);             // initial s, q
    for (int it = 0; it < 3; it++) {
        k_attn<<<dim3(8, 8), 256>>>();
        k_updmlp<<<32, 512>>>(ln_m_g, ln_m_b, mlp_w1, mlp_b1, mlp_w2, mlp_b2,
                              q_w, ln_s_g, ln_s_b);          // + next-iter LN/q fused
    }

    k_dec1<<<32, 512>>>(dec_w1, dec_b1, dec_w2, dec_b2);
    k_rbar<<<16, 256>>>();
    k_recon<<<32, 128>>>(dec_w3, dec_b3);
    k_loss<<<1, 1024>>>(out, out_size);
    k_copy_out<<<128, 256>>>(out, out_size);
}

// round 17
// speedup vs baseline: 1.5806x; 1.0026x over previous
#include <cuda_runtime.h>
#include <cuda_bf16.h>
#include <math.h>

#define NB     8
#define TT     4096
#define HID    4096
#define NSAMP  512
#define NSLOT  16
#define DD     256
#define BOTD   512
#define EPSF   1e-5f
#define NSLICE 256          // full K=4096, 16 per slice
#define NGEMMB 128          // 32 row tiles x 4 col tiles
#define NMEANB 2048
#define NCHUNK 16           // attn chunks (32 rows each)

typedef unsigned int u32;

// ---------------- scratch (no allocations allowed) ----------------
__device__ float g_pre    [NB*NSAMP*DD];
__device__ float g_x      [NB*NSAMP*DD];
__device__ float g_k      [NB*NSAMP*DD];
__device__ float g_v      [NB*NSAMP*DD];
__device__ int   g_idx    [NSAMP];
__device__ float g_tpart  [64*NB*HID];
__device__ float g_target [NB*HID];
__device__ float g_slots  [NB*NSLOT*DD];
__device__ float g_s      [NB*NSLOT*DD];
__device__ float g_q      [NB*NSLOT*DD];
__device__ float g_updpart[NB*NCHUNK*NSLOT*DD];
__device__ float g_r2     [NB*NSLOT*BOTD];
__device__ float g_rbar   [NB*BOTD];
__device__ float g_recon  [NB*HID];

// ---------------- helpers ----------------
__device__ __forceinline__ float warpSum(float v){
#pragma unroll
    for (int o = 16; o > 0; o >>= 1) v += __shfl_xor_sync(0xffffffffu, v, o);
    return v;
}
__device__ __forceinline__ float geluf(float x){
    return 0.5f * x * (1.0f + erff(x * 0.7071067811865475f));
}
__device__ __forceinline__ u32 smem_u32(const void* p){
    return (u32)__cvta_generic_to_shared(p);
}
__device__ __forceinline__ u32 packbf2(float x0, float x1){
    __nv_bfloat162 p = __floats2bfloat162_rn(x0, x1);
    return *(u32*)&p;
}
__device__ __forceinline__ void ldsm4(u32& r0, u32& r1, u32& r2, u32& r3, u32 addr){
    asm volatile("ldmatrix.sync.aligned.m8n8.x4.shared.b16 {%0,%1,%2,%3},[%4];\n"
        : "=r"(r0), "=r"(r1), "=r"(r2), "=r"(r3) : "r"(addr));
}
__device__ __forceinline__ void ldsm2t(u32& r0, u32& r1, u32 addr){
    asm volatile("ldmatrix.sync.aligned.m8n8.x2.trans.shared.b16 {%0,%1},[%2];\n"
        : "=r"(r0), "=r"(r1) : "r"(addr));
}
__device__ __forceinline__ void mma16816(float* c, const u32* a, const u32* b){
    asm volatile(
        "mma.sync.aligned.m16n8k16.row.col.f32.bf16.bf16.f32 "
        "{%0,%1,%2,%3},{%4,%5,%6,%7},{%8,%9},{%0,%1,%2,%3};\n"
        : "+f"(c[0]), "+f"(c[1]), "+f"(c[2]), "+f"(c[3])
        : "r"(a[0]), "r"(a[1]), "r"(a[2]), "r"(a[3]), "r"(b[0]), "r"(b[1]));
}

// ---------------- idx = concat(linspace(0,T-256,256).astype(i32), arange(T-256,T)) ----------------
__global__ void k_init_idx(){
    int i = threadIdx.x;
    if (i < 256) {
        const float delta = 3840.0f / 255.0f;     // fp32, matches jnp.linspace step
        g_idx[i] = (int)((float)i * delta);       // truncation == astype(int32)
    } else {
        g_idx[i] = 3840 + (i - 256);
    }
}

// ===========================================================================
// k_front: 2176 blocks of 256 threads, 2 blocks/SM.
//   bid <  128 : full-K gather GEMM on tensor cores (bf16 hi/lo, 128x64 tile,
//                K=4096 in one block, bias in epilogue -> g_pre). 1 per SM.
//   bid >= 128 : mean partial (64 t-steps x 1024 h) streaming in slot 2.
// ===========================================================================
#define A_STR 24   // bf16 elems per A smem row (16 data + 8 pad)
#define B_STR 72   // bf16 elems per B smem row (64 data + 8 pad)

__global__ void __launch_bounds__(256, 2) k_front(const float* __restrict__ hs,
                                                  const float* __restrict__ Bw,
                                                  const float* __restrict__ bias){
    __shared__ __align__(16) __nv_bfloat16 sAh[2][128*A_STR];
    __shared__ __align__(16) __nv_bfloat16 sAl[2][128*A_STR];
    __shared__ __align__(16) __nv_bfloat16 sBh[2][16*B_STR];
    __shared__ __align__(16) __nv_bfloat16 sBl[2][16*B_STR];

    int bid = blockIdx.x;
    int tid = threadIdx.x;

    if (bid >= NGEMMB) {
        // ---------------- mean partial: 64 t-steps x 1024 h ----------------
        int mid = bid - NGEMMB;             // 0..2047
        int hb = (mid & 3) * 1024 + tid * 4;
        int b  = (mid >> 2) & 7;
        int c  = mid >> 5;                  // 0..63
        const float* p = hs + ((size_t)b*TT + (size_t)c*64)*HID + hb;
        float4 acc0 = make_float4(0,0,0,0), acc1 = make_float4(0,0,0,0);
#pragma unroll 4
        for (int t = 0; t < 64; t += 2) {
            float4 v0 = *(const float4*)(p + (size_t)t*HID);
            float4 v1 = *(const float4*)(p + (size_t)(t+1)*HID);
            acc0.x += v0.x; acc0.y += v0.y; acc0.z += v0.z; acc0.w += v0.w;
            acc1.x += v1.x; acc1.y += v1.y; acc1.z += v1.z; acc1.w += v1.w;
        }
        float4 acc = make_float4(acc0.x+acc1.x, acc0.y+acc1.y, acc0.z+acc1.z, acc0.w+acc1.w);
        *(float4*)&g_tpart[((size_t)c*NB + b)*HID + hb] = acc;
        return;
    }

    // ---------------- tensor-core gather GEMM block (full K) ----------------
    int ct   = bid & 3;                     // col tile (64 wide)
    int rt   = bid >> 2;                    // row tile (128 rows)
    int bcol = ct * 64;
    int brow = rt * 128;

    // A: thread t loads 8 fp32 of gathered row (t>>1), half (t&1)
    int ar = tid >> 1, ah = tid & 1;
    int rg = brow + ar;
    const float* gA = hs + ((size_t)((rg >> 9)*TT + g_idx[rg & 511]))*HID + ah*8;
    // B: thread t loads 4 fp32 of in_w row (t>>4), cols (t&15)*4
    int bk = tid >> 4, bc = (tid & 15) * 4;
    const float* gB = Bw + (size_t)bk*256 + bcol + bc;

    __nv_bfloat16* aDstH[2] = { &sAh[0][ar*A_STR + ah*8], &sAh[1][ar*A_STR + ah*8] };
    __nv_bfloat16* aDstL[2] = { &sAl[0][ar*A_STR + ah*8], &sAl[1][ar*A_STR + ah*8] };
    __nv_bfloat16* bDstH[2] = { &sBh[0][bk*B_STR + bc],   &sBh[1][bk*B_STR + bc] };
    __nv_bfloat16* bDstL[2] = { &sBl[0][bk*B_STR + bc],   &sBl[1][bk*B_STR + bc] };

    int warp = tid >> 5, lane = tid & 31;
    int wm = warp >> 2;          // 0..1 : 64-row half
    int wn = warp & 3;           // 0..3 : 16-col strip
    int aRowL = (lane & 7) + ((lane >> 3) & 1) * 8;
    int aKoff = (lane >> 4) * 8;
    u32 aOffLane = (u32)((aRowL*A_STR + aKoff) * 2);
    u32 bOffLane = (u32)(((lane & 15)*B_STR) * 2);
    u32 aBaseH[2] = { smem_u32(&sAh[0][0]), smem_u32(&sAh[1][0]) };
    u32 aBaseL[2] = { smem_u32(&sAl[0][0]), smem_u32(&sAl[1][0]) };
    u32 bBaseH[2] = { smem_u32(&sBh[0][0]), smem_u32(&sBh[1][0]) };
    u32 bBaseL[2] = { smem_u32(&sBl[0][0]), smem_u32(&sBl[1][0]) };

    float acc[4][2][4];
#pragma unroll
    for (int i = 0; i < 4; i++)
#pragma unroll
        for (int j = 0; j < 2; j++)
#pragma unroll
            for (int r = 0; r < 4; r++) acc[i][j][r] = 0.f;

    float apf[8]; float bpf[4];

    // prologue: load slice 0
    {
        float4 a0 = *(const float4*)(gA);
        float4 a1 = *(const float4*)(gA + 4);
        apf[0]=a0.x; apf[1]=a0.y; apf[2]=a0.z; apf[3]=a0.w;
        apf[4]=a1.x; apf[5]=a1.y; apf[6]=a1.z; apf[7]=a1.w;
        float4 b0 = *(const float4*)(gB);
        bpf[0]=b0.x; bpf[1]=b0.y; bpf[2]=b0.z; bpf[3]=b0.w;
    }
    {
        u32 h[4], l[4];
#pragma unroll
        for (int j = 0; j < 4; j++) {
            float x0 = apf[2*j], x1 = apf[2*j+1];
            __nv_bfloat16 h0 = __float2bfloat16(x0), h1 = __float2bfloat16(x1);
            float l0 = x0 - __bfloat162float(h0), l1 = x1 - __bfloat162float(h1);
            h[j] = packbf2(__bfloat162float(h0), __bfloat162float(h1));
            l[j] = packbf2(l0, l1);
        }
        *(uint4*)aDstH[0] = make_uint4(h[0],h[1],h[2],h[3]);
        *(uint4*)aDstL[0] = make_uint4(l[0],l[1],l[2],l[3]);
        u32 bh[2], bl[2];
#pragma unroll
        for (int j = 0; j < 2; j++) {
            float x0 = bpf[2*j], x1 = bpf[2*j+1];
            __nv_bfloat16 h0 = __float2bfloat16(x0), h1 = __float2bfloat16(x1);
            float l0 = x0 - __bfloat162float(h0), l1 = x1 - __bfloat162float(h1);
            bh[j] = packbf2(__bfloat162float(h0), __bfloat162float(h1));
            bl[j] = packbf2(l0, l1);
        }
        *(uint2*)bDstH[0] = make_uint2(bh[0], bh[1]);
        *(uint2*)bDstL[0] = make_uint2(bl[0], bl[1]);
    }
    // prefetch slice 1
    {
        float4 a0 = *(const float4*)(gA + 16);
        float4 a1 = *(const float4*)(gA + 20);
        apf[0]=a0.x; apf[1]=a0.y; apf[2]=a0.z; apf[3]=a0.w;
        apf[4]=a1.x; apf[5]=a1.y; apf[6]=a1.z; apf[7]=a1.w;
        float4 b0 = *(const float4*)(gB + (size_t)16*256);
        bpf[0]=b0.x; bpf[1]=b0.y; bpf[2]=b0.z; bpf[3]=b0.w;
    }
    __syncthreads();

    int buf = 0;
#pragma unroll 1
    for (int s = 0; s < NSLICE; s++) {
        // ---- mma on buf ----
        u32 af[2][4][4];
#pragma unroll
        for (int mf = 0; mf < 4; mf++) {
            u32 ao = (u32)((wm*64 + mf*16)*A_STR*2) + aOffLane;
            ldsm4(af[0][mf][0], af[0][mf][1], af[0][mf][2], af[0][mf][3], aBaseH[buf] + ao);
            ldsm4(af[1][mf][0], af[1][mf][1], af[1][mf][2], af[1][mf][3], aBaseL[buf] + ao);
        }
        u32 bfr[2][2][2];
#pragma unroll
        for (int nf = 0; nf < 2; nf++) {
            u32 bo = bOffLane + (u32)((wn*16 + nf*8)*2);
            ldsm2t(bfr[0][nf][0], bfr[0][nf][1], bBaseH[buf] + bo);
            ldsm2t(bfr[1][nf][0], bfr[1][nf][1], bBaseL[buf] + bo);
        }
#pragma unroll
        for (int mf = 0; mf < 4; mf++) {
#pragma unroll
            for (int nf = 0; nf < 2; nf++) {
                mma16816(acc[mf][nf], af[0][mf], bfr[0][nf]);   // hi @ hi
                mma16816(acc[mf][nf], af[0][mf], bfr[1][nf]);   // hi @ lo
                mma16816(acc[mf][nf], af[1][mf], bfr[0][nf]);   // lo @ hi
            }
        }
        // ---- stage slice s+1 into buf^1, prefetch s+2 ----
        if (s < NSLICE - 1) {
            int nb = buf ^ 1;
            u32 h[4], l[4];
#pragma unroll
            for (int j = 0; j < 4; j++) {
                float x0 = apf[2*j], x1 = apf[2*j+1];
                __nv_bfloat16 h0 = __float2bfloat16(x0), h1 = __float2bfloat16(x1);
                float l0 = x0 - __bfloat162float(h0), l1 = x1 - __bfloat162float(h1);
                h[j] = packbf2(__bfloat162float(h0), __bfloat162float(h1));
                l[j] = packbf2(l0, l1);
            }
            *(uint4*)aDstH[nb] = make_uint4(h[0],h[1],h[2],h[3]);
            *(uint4*)aDstL[nb] = make_uint4(l[0],l[1],l[2],l[3]);
            u32 bh[2], bl[2];
#pragma unroll
            for (int j = 0; j < 2; j++) {
                float x0 = bpf[2*j], x1 = bpf[2*j+1];
                __nv_bfloat16 h0 = __float2bfloat16(x0), h1 = __float2bfloat16(x1);
                float l0 = x0 - __bfloat162float(h0), l1 = x1 - __bfloat162float(h1);
                bh[j] = packbf2(__bfloat162float(h0), __bfloat162float(h1));
                bl[j] = packbf2(l0, l1);
            }
            *(uint2*)bDstH[nb] = make_uint2(bh[0], bh[1]);
            *(uint2*)bDstL[nb] = make_uint2(bl[0], bl[1]);
            if (s < NSLICE - 2) {
                int ko = (s + 2) * 16;
                float4 a0 = *(const float4*)(gA + ko);
                float4 a1 = *(const float4*)(gA + ko + 4);
                apf[0]=a0.x; apf[1]=a0.y; apf[2]=a0.z; apf[3]=a0.w;
                apf[4]=a1.x; apf[5]=a1.y; apf[6]=a1.z; apf[7]=a1.w;
                float4 b0 = *(const float4*)(gB + (size_t)ko*256);
                bpf[0]=b0.x; bpf[1]=b0.y; bpf[2]=b0.z; bpf[3]=b0.w;
            }
            __syncthreads();
            buf = nb;
        }
    }

    // ---- epilogue: bias + write g_pre ----
    int cr = lane >> 2, cc = (lane & 3) * 2;
#pragma unroll
    for (int mf = 0; mf < 4; mf++) {
#pragma unroll
        for (int nf = 0; nf < 2; nf++) {
            int row0 = brow + wm*64 + mf*16 + cr;
            int col  = bcol + wn*16 + nf*8 + cc;
            float b0 = bias[col], b1 = bias[col+1];
            *(float2*)&g_pre[(size_t)row0*256 + col]     = make_float2(acc[mf][nf][0]+b0, acc[mf][nf][1]+b1);
            *(float2*)&g_pre[(size_t)(row0+8)*256 + col] = make_float2(acc[mf][nf][2]+b0, acc[mf][nf][3]+b1);
        }
    }
}

__global__ void k_mean_reduce(){
    int gi = blockIdx.x * 256 + threadIdx.x;   // gi = b*HID + h, 32768 total
    float s = 0.f;
#pragma unroll
    for (int c = 0; c < 64; c++) s += g_tpart[(size_t)c*NB*HID + gi];
    g_target[gi] = s * (1.0f / (float)TT);
}

// ---------------- LayerNorm g_pre -> g_x ----------------
__global__ void __launch_bounds__(256) k_ln2(const float* __restrict__ gg, const float* __restrict__ bb){
    __shared__ float buf[256];
    int r = blockIdx.x, tid = threadIdx.x;
    float v = g_pre[(size_t)r*256 + tid];
    buf[tid] = v; __syncthreads();
    for (int s = 128; s > 0; s >>= 1) { if (tid < s) buf[tid] += buf[tid + s]; __syncthreads(); }
    float mu = buf[0] * (1.f/256.f); __syncthreads();
    float d = v - mu;
    buf[tid] = d * d; __syncthreads();
    for (int s = 128; s > 0; s >>= 1) { if (tid < s) buf[tid] += buf[tid + s]; __syncthreads(); }
    float var = buf[0] * (1.f/256.f);
    g_x[(size_t)r*256 + tid] = d * rsqrtf(var + EPSF) * gg[tid] + bb[tid];
}

// ---------------- k/v projections: grid (4, 64, 2), K=256, double-buffered ----------------
__global__ void __launch_bounds__(256) k_gemmkv(const float* __restrict__ kw,
                                                const float* __restrict__ vw){
    __shared__ __align__(16) float As[2][16][64];
    __shared__ __align__(16) float Bs[2][16][64];
    int tid  = threadIdx.x;
    int bcol = blockIdx.x * 64, brow = blockIdx.y * 64;
    const float* Bw = blockIdx.z ? vw : kw;
    float* C        = blockIdx.z ? g_v : g_k;
    int arow = tid >> 2, ak = (tid & 3) * 4;
    const float* Arow = g_x + (size_t)(brow + arow) * DD;
    int brr = tid >> 4, bc = (tid & 15) * 4;
    int ty  = tid >> 4, tx = tid & 15;
    float acc[4][4] = {};

    float4 a4 = *(const float4*)(Arow + ak);
    float4 b4 = *(const float4*)(Bw + (size_t)brr*256 + bcol + bc);
    As[0][ak+0][arow] = a4.x; As[0][ak+1][arow] = a4.y;
    As[0][ak+2][arow] = a4.z; As[0][ak+3][arow] = a4.w;
    *(float4*)&Bs[0][brr][bc] = b4;
    __syncthreads();

    int buf = 0;
#pragma unroll 1
    for (int kt = 0; kt < 16; kt++) {
        if (kt < 15) {
            a4 = *(const float4*)(Arow + (kt+1)*16 + ak);
            b4 = *(const float4*)(Bw + (size_t)((kt+1)*16 + brr)*256 + bcol + bc);
        }
#pragma unroll
        for (int kk = 0; kk < 16; kk++) {
            float4 av = *(const float4*)&As[buf][kk][ty*4];
            float4 bv = *(const float4*)&Bs[buf][kk][tx*4];
            acc[0][0]+=av.x*bv.x; acc[0][1]+=av.x*bv.y; acc[0][2]+=av.x*bv.z; acc[0][3]+=av.x*bv.w;
            acc[1][0]+=av.y*bv.x; acc[1][1]+=av.y*bv.y; acc[1][2]+=av.y*bv.z; acc[1][3]+=av.y*bv.w;
            acc[2][0]+=av.z*bv.x; acc[2][1]+=av.z*bv.y; acc[2][2]+=av.z*bv.z; acc[2][3]+=av.z*bv.w;
            acc[3][0]+=av.w*bv.x; acc[3][1]+=av.w*bv.y; acc[3][2]+=av.w*bv.z; acc[3][3]+=av.w*bv.w;
        }
        if (kt < 15) {
            int nb = buf ^ 1;
            As[nb][ak+0][arow] = a4.x; As[nb][ak+1][arow] = a4.y;
            As[nb][ak+2][arow] = a4.z; As[nb][ak+3][arow] = a4.w;
            *(float4*)&Bs[nb][brr][bc] = b4;
            buf = nb;
            __syncthreads();
        }
    }
#pragma unroll
    for (int i = 0; i < 4; i++)
#pragma unroll
        for (int j = 0; j < 4; j++)
            C[(size_t)(brow + ty*4 + i)*256 + bcol + tx*4 + j] = acc[i][j];
}

// ---------------- slots init ----------------
__global__ void k_copy_in(const float* __restrict__ src){
    int i = blockIdx.x * 256 + threadIdx.x;
    g_slots[i] = src[i];
}

// ---------------- initial: s=LN(slots), q=s@q_w (4 rows per block) ----------------
__global__ void __launch_bounds__(256) k_slotlnq(const float* __restrict__ qw,
                                                 const float* __restrict__ lg,
                                                 const float* __restrict__ lb){
    __shared__ float sm[4][256];
    int tid = threadIdx.x, warp = tid >> 5, lane = tid & 31;
    int b = blockIdx.x >> 2, r0 = (blockIdx.x & 3) * 4;
    if (warp < 4) {
        int row = b*16 + r0 + warp;
        float v[8]; float s1 = 0.f;
#pragma unroll
        for (int j = 0; j < 8; j++) { v[j] = g_slots[(size_t)row*256 + lane + 32*j]; s1 += v[j]; }
        s1 = warpSum(s1); float mu = s1 * (1.f/256.f);
        float s2 = 0.f;
#pragma unroll
        for (int j = 0; j < 8; j++) { float dd = v[j] - mu; s2 += dd*dd; }
        s2 = warpSum(s2); float rs = rsqrtf(s2 * (1.f/256.f) + EPSF);
#pragma unroll
        for (int j = 0; j < 8; j++) {
            int d = lane + 32*j;
            float sv = (v[j] - mu) * rs * lg[d] + lb[d];
            sm[warp][d] = sv;
            g_s[(size_t)row*256 + d] = sv;
        }
    }
    __syncthreads();
    float a0=0,a1=0,a2=0,a3=0;
    for (int d = 0; d < 256; d++) {
        float w = qw[(size_t)d*256 + tid];
        a0 += sm[0][d]*w; a1 += sm[1][d]*w; a2 += sm[2][d]*w; a3 += sm[3][d]*w;
    }
    int base = (b*16 + r0) * 256;
    g_q[base       + tid] = a0;
    g_q[base + 256 + tid] = a1;
    g_q[base + 512 + tid] = a2;
    g_q[base + 768 + tid] = a3;
}

// ---------------- logits + softmax(over slots) + partial upd: 32-row chunks ----------------
__global__ void __launch_bounds__(256) k_attn(){
    __shared__ __align__(16) float qs[16][260];
    __shared__ __align__(16) float ksh[8][260];
    __shared__ float attn_s[32][16];
    int tid = threadIdx.x;
    int chunk = blockIdx.x, b = blockIdx.y;
#pragma unroll
    for (int i = 0; i < 16; i++) qs[i][tid] = g_q[(size_t)(b*NSLOT + i)*DD + tid];
    __syncthreads();
    int warp = tid >> 5, lane = tid & 31;
    for (int step = 0; step < 4; step++) {
        int nl = step*8 + warp;
        const float* kr = g_k + ((size_t)(b*NSAMP + chunk*32 + nl))*DD;
#pragma unroll
        for (int j = 0; j < 8; j++) ksh[warp][lane + 32*j] = kr[lane + 32*j];
        __syncwarp();
        float logit = -1e30f;
        if (lane < 16) {
            float a = 0.f;
#pragma unroll 8
            for (int d = 0; d < 256; d += 4) {
                float4 qv = *(const float4*)&qs[lane][d];
                float4 kv = *(const float4*)&ksh[warp][d];
                a += qv.x*kv.x + qv.y*kv.y + qv.z*kv.z + qv.w*kv.w;
            }
            logit = a * 0.0625f;           // D^-0.5
        }
        float m = logit;
#pragma unroll
        for (int o = 8; o > 0; o >>= 1) m = fmaxf(m, __shfl_xor_sync(0xffffffffu, m, o));
        float e = expf(logit - m);
        float ss = e;
#pragma unroll
        for (int o = 8; o > 0; o >>= 1) ss += __shfl_xor_sync(0xffffffffu, ss, o);
        if (lane < 16) attn_s[nl][lane] = e / ss;
        __syncwarp();
    }
    __syncthreads();
    float acc[16];
#pragma unroll
    for (int kk = 0; kk < 16; kk++) acc[kk] = 0.f;
    for (int nl = 0; nl < 32; nl++) {
        float vv = g_v[((size_t)(b*NSAMP + chunk*32 + nl))*DD + tid];
#pragma unroll
        for (int kk = 0; kk < 16; kk++) acc[kk] += attn_s[nl][kk] * vv;
    }
#pragma unroll
    for (int kk = 0; kk < 16; kk++)
        g_updpart[((size_t)(b*NCHUNK + chunk))*(NSLOT*DD) + kk*DD + tid] = acc[kk];
}

// ---------------- reduce partials + LN + MLP + slot update + next-iter LN/q (2 rows/block, 64 blocks) ----------------
__global__ void __launch_bounds__(512) k_updmlp(const float* __restrict__ lmg, const float* __restrict__ lmb,
                                                const float* __restrict__ w1,  const float* __restrict__ b1,
                                                const float* __restrict__ w2,  const float* __restrict__ b2,
                                                const float* __restrict__ qw,
                                                const float* __restrict__ lsg, const float* __restrict__ lsb){
    __shared__ float usm[2][256];
    __shared__ float hsm[2][256];
    __shared__ float gsm[2][512];
    int tid = threadIdx.x;
    int b = blockIdx.x >> 3, r0 = (blockIdx.x & 7) * 2;   // 64 blocks: b 0..7, r0 0..14
    {
        int row = tid >> 8, d = tid & 255;
        float u = 0.f;
#pragma unroll
        for (int c = 0; c < NCHUNK; c++)
            u += g_updpart[((size_t)(b*NCHUNK + c))*(NSLOT*DD) + (size_t)(r0 + row)*DD + d];
        usm[row][d] = u;
    }
    __syncthreads();
    int warp = tid >> 5, lane = tid & 31;
    if (warp < 2) {
        float v[8]; float s1 = 0.f;
#pragma unroll
        for (int j = 0; j < 8; j++) { v[j] = usm[warp][lane + 32*j]; s1 += v[j]; }
        s1 = warpSum(s1); float mu = s1 * (1.f/256.f);
        float s2 = 0.f;
#pragma unroll
        for (int j = 0; j < 8; j++) { float dd = v[j] - mu; s2 += dd*dd; }
        s2 = warpSum(s2); float rs = rsqrtf(s2 * (1.f/256.f) + EPSF);
#pragma unroll
        for (int j = 0; j < 8; j++) {
            int d = lane + 32*j;
            hsm[warp][d] = (v[j] - mu) * rs * lmg[d] + lmb[d];
        }
    }
    __syncthreads();
    float a0 = b1[tid], a1 = a0;
    for (int d = 0; d < 256; d++) {
        float w = w1[(size_t)d*512 + tid];
        a0 += hsm[0][d]*w; a1 += hsm[1][d]*w;
    }
    gsm[0][tid] = geluf(a0); gsm[1][tid] = geluf(a1);
    __syncthreads();
    int base = (b*16 + r0) * 256;
    if (tid < 256) {
        float m0=0,m1=0;
        for (int j = 0; j < 512; j++) {
            float w = w2[(size_t)j*256 + tid];
            m0 += gsm[0][j]*w; m1 += gsm[1][j]*w;
        }
        float bb = b2[tid];
        float n0 = g_s[base       + tid] + m0 + bb;
        float n1 = g_s[base + 256 + tid] + m1 + bb;
        g_slots[base       + tid] = n0;
        g_slots[base + 256 + tid] = n1;
        usm[0][tid] = n0; usm[1][tid] = n1;
    }
    __syncthreads();
    // ---- next iteration's s = LN(slots) and q = s @ q_w (fused epilogue) ----
    if (warp < 2) {
        float v[8]; float s1 = 0.f;
#pragma unroll
        for (int j = 0; j < 8; j++) { v[j] = usm[warp][lane + 32*j]; s1 += v[j]; }
        s1 = warpSum(s1); float mu = s1 * (1.f/256.f);
        float s2 = 0.f;
#pragma unroll
        for (int j = 0; j < 8; j++) { float dd = v[j] - mu; s2 += dd*dd; }
        s2 = warpSum(s2); float rs = rsqrtf(s2 * (1.f/256.f) + EPSF);
#pragma unroll
        for (int j = 0; j < 8; j++) {
            int d = lane + 32*j;
            float sv = (v[j] - mu) * rs * lsg[d] + lsb[d];
            hsm[warp][d] = sv;
            g_s[(size_t)(b*16 + r0 + warp)*256 + d] = sv;
        }
    }
    __syncthreads();
    if (tid < 256) {
        float q0=0,q1=0;
        for (int d = 0; d < 256; d++) {
            float w = qw[(size_t)d*256 + tid];
            q0 += hsm[0][d]*w; q1 += hsm[1][d]*w;
        }
        g_q[base       + tid] = q0;
        g_q[base + 256 + tid] = q1;
    }
}

// ---------------- decoder stage 1+2 (2 rows / block) ----------------
__global__ void __launch_bounds__(512) k_dec1(const float* __restrict__ w1, const float* __restrict__ b1,
                                              const float* __restrict__ w2, const float* __restrict__ b2){
    __shared__ float ssm[2][256];
    __shared__ float g1[2][512];
    int tid = threadIdx.x;
    int r0 = blockIdx.x * 2;
    if (tid < 512)
        ssm[tid >> 8][tid & 255] = g_slots[(size_t)(r0 + (tid >> 8))*256 + (tid & 255)];
    __syncthreads();
    float a0 = b1[tid], a1 = a0;
    for (int d = 0; d < 256; d++) {
        float w = w1[(size_t)d*512 + tid];
        a0 += ssm[0][d]*w; a1 += ssm[1][d]*w;
    }
    g1[0][tid] = geluf(a0); g1[1][tid] = geluf(a1);
    __syncthreads();
    float c0 = b2[tid], c1 = c0;
    for (int j = 0; j < 512; j++) {
        float w = w2[(size_t)j*512 + tid];
        c0 += g1[0][j]*w; c1 += g1[1][j]*w;
    }
    g_r2[(size_t)(r0+0)*512 + tid] = geluf(c0);
    g_r2[(size_t)(r0+1)*512 + tid] = geluf(c1);
}

__global__ void k_rbar(){
    int gi = blockIdx.x * 256 + threadIdx.x;   // 4096 = 8 * 512
    int b = gi >> 9, j = gi & 511;
    float s = 0.f;
#pragma unroll
    for (int kk = 0; kk < 16; kk++) s += g_r2[(size_t)(b*16 + kk)*512 + j];
    g_rbar[gi] = s * (1.f/16.f);
}

__global__ void __launch_bounds__(128) k_recon(const float* __restrict__ w3, const float* __restrict__ b3){
    __shared__ float rb[8][512];
    int tid = threadIdx.x;
    for (int idx = tid; idx < 4096; idx += 128) rb[idx >> 9][idx & 511] = g_rbar[idx];
    __syncthreads();
    int h = blockIdx.x * 128 + tid;
    float bv = b3[h];
    float acc[8];
#pragma unroll
    for (int b = 0; b < 8; b++) acc[b] = bv;
    for (int j = 0; j < 512; j++) {
        float w = w3[(size_t)j*HID + h];
#pragma unroll
        for (int b = 0; b < 8; b++) acc[b] += rb[b][j] * w;
    }
#pragma unroll
    for (int b = 0; b < 8; b++) g_recon[(size_t)b*HID + h] = acc[b];
}

__global__ void __launch_bounds__(1024) k_loss(float* __restrict__ out, int out_size){
    __shared__ float buf[1024];
    int tid = threadIdx.x;
    float s = 0.f;
    for (int i = tid; i < NB*HID; i += 1024) {
        float dd = g_recon[i] - g_target[i];
        s += dd * dd;
    }
    buf[tid] = s; __syncthreads();
    for (int st = 512; st > 0; st >>= 1) { if (tid < st) buf[tid] += buf[tid + st]; __syncthreads(); }
    if (tid == 0) out[out_size - 1] = buf[0] * (1.f / (float)(NB*HID));
}

__global__ void k_copy_out(float* __restrict__ out, int out_size){
    int i = blockIdx.x * 256 + threadIdx.x;
    if (i < NB*NSLOT*DD && i < out_size) out[i] = g_slots[i];
}

// ---------------- launcher ----------------
extern "C" void kernel_launch(void* const* d_in, const int* in_sizes, int n_in,
                              void* d_out, int out_size){
    const float* hs        = (const float*)d_in[0];
    const float* old_slots = (const float*)d_in[1];
    const float* in_w      = (const float*)d_in[2];
    const float* in_b      = (const float*)d_in[3];
    const float* ln_in_g   = (const float*)d_in[4];
    const float* ln_in_b   = (const float*)d_in[5];
    const float* ln_s_g    = (const float*)d_in[6];
    const float* ln_s_b    = (const float*)d_in[7];
    const float* ln_m_g    = (const float*)d_in[8];
    const float* ln_m_b    = (const float*)d_in[9];
    const float* q_w       = (const float*)d_in[10];
    const float* k_w       = (const float*)d_in[11];
    const float* v_w       = (const float*)d_in[12];
    const float* mlp_w1    = (const float*)d_in[13];
    const float* mlp_b1    = (const float*)d_in[14];
    const float* mlp_w2    = (const float*)d_in[15];
    const float* mlp_b2    = (const float*)d_in[16];
    const float* dec_w1    = (const float*)d_in[17];
    const float* dec_b1    = (const float*)d_in[18];
    const float* dec_w2    = (const float*)d_in[19];
    const float* dec_b2    = (const float*)d_in[20];
    const float* dec_w3    = (const float*)d_in[21];
    const float* dec_b3    = (const float*)d_in[22];
    float* out = (float*)d_out;

    k_init_idx<<<1, 512>>>();

    // fused front: 128 full-K tensor-core GEMM blocks (first) + 2048 mean blocks
    k_front<<<NGEMMB + NMEANB, 256>>>(hs, in_w, in_b);
    k_ln2<<<NB*NSAMP, 256>>>(ln_in_g, ln_in_b);              // LN(g_pre) -> g_x
    k_mean_reduce<<<128, 256>>>();
    k_gemmkv<<<dim3(4, 64, 2), 256>>>(k_w, v_w);             // k and v in one launch

    k_copy_in<<<128, 256>>>(old_slots);
    k_slotlnq<<<32, 256>>>(q_w, ln_s_g, ln_s_b);             // initial s, q
    for (int it = 0; it < 3; it++) {
        k_attn<<<dim3(NCHUNK, 8), 256>>>();
        k_updmlp<<<64, 512>>>(ln_m_g, ln_m_b, mlp_w1, mlp_b1, mlp_w2, mlp_b2,
                              q_w, ln_s_g, ln_s_b);          // FIX: 64 blocks (was 128)
    }

    k_dec1<<<64, 512>>>(dec_w1, dec_b1, dec_w2, dec_b2);
    k_rbar<<<16, 256>>>();
    k_recon<<<32, 128>>>(dec_w3, dec_b3);
    k_loss<<<1, 1024>>>(out, out_size);
    k_copy_out<<<128, 256>>>(out, out_size);
}